// round 5
// baseline (speedup 1.0000x reference)
#include <cuda_runtime.h>
#include <cuda_bf16.h>
#include <math.h>
#include <stdint.h>

// Problem constants
#define S_LEN 2048
#define HID   2048
#define NH    16
#define DH    256
#define RR    64
#define NOPE  192
#define QL    1024
#define ORANK 512
#define NG    4
#define HD    (NH*DH)    // 4096
#define GO    (NG*ORANK) // 2048
#define EPSF  1e-6f
#define SCALE_F 0.0625f  // 256^-0.5

// ---------------- scratch (static device globals; no allocation) ----------------
__device__ float g_qlat[S_LEN * QL];    // 8 MB
__device__ float g_q   [S_LEN * HD];    // 32 MB
__device__ float g_kv  [S_LEN * DH];    // 2 MB
__device__ float g_o   [S_LEN * HD];    // 32 MB
__device__ float g_or  [S_LEN * GO];    // 16 MB

// =================== helpers ===================
__device__ __forceinline__ uint32_t smem_u32(const void* p) {
    uint32_t a;
    asm("{ .reg .u64 t; cvta.to.shared.u64 t, %1; cvt.u32.u64 %0, t; }" : "=r"(a) : "l"(p));
    return a;
}
__device__ __forceinline__ void cp_async16(uint32_t dst, const void* src) {
    asm volatile("cp.async.cg.shared.global [%0], [%1], 16;" :: "r"(dst), "l"(src));
}
#define CP_COMMIT() asm volatile("cp.async.commit_group;" ::: "memory")
#define CP_WAIT1()  asm volatile("cp.async.wait_group 1;" ::: "memory")

__device__ __forceinline__ uint32_t f2tf32(float x) {
    uint32_t r;
    asm("cvt.rna.tf32.f32 %0, %1;" : "=r"(r) : "f"(x));
    return r;
}
__device__ __forceinline__ void mma_tf32(float* d, const uint32_t* a, const uint32_t* b) {
    asm volatile(
        "mma.sync.aligned.m16n8k8.row.col.f32.tf32.tf32.f32 "
        "{%0,%1,%2,%3}, {%4,%5,%6,%7}, {%8,%9}, {%0,%1,%2,%3};"
        : "+f"(d[0]), "+f"(d[1]), "+f"(d[2]), "+f"(d[3])
        : "r"(a[0]), "r"(a[1]), "r"(a[2]), "r"(a[3]), "r"(b[0]), "r"(b[1]));
}

// ---------------- block reduction (256 threads) ----------------
__device__ __forceinline__ float blk_sum_256(float v) {
    __shared__ float red[8];
    #pragma unroll
    for (int o = 16; o; o >>= 1) v += __shfl_xor_sync(0xffffffffu, v, o);
    if ((threadIdx.x & 31) == 0) red[threadIdx.x >> 5] = v;
    __syncthreads();
    float t = 0.f;
    #pragma unroll
    for (int i = 0; i < 8; i++) t += red[i];
    return t;
}

// =================== tf32 mma.sync GEMM: C[M,N] = A[M,K] * B[N,K]^T ===================
// CTA tile 128x128, K-chunk 32, 8 warps (2m x 4n), each warp 64x32.
// SMEM rows stride 36 floats -> conflict-free fragment LDS.
#define ASTRIDE 36
#define STG_FLOATS (128 * ASTRIDE)        // per operand per stage
#define STG_BYTES  (STG_FLOATS * 4)       // 18432
#define FULL_STAGE (2 * STG_BYTES)        // 36864 (A + B)
#define GEMM_SMEM  (2 * FULL_STAGE)       // 73728

__global__ void __launch_bounds__(256, 2) gemm_mma_kernel(
    const float* __restrict__ A, const float* __restrict__ B, float* __restrict__ C,
    int K, int lda, int ldb, int ldc, int grpN, int grpStride)
{
    extern __shared__ __align__(16) float smem[];
    const int tid = threadIdx.x, lane = tid & 31, wid = tid >> 5;
    const int m0 = blockIdx.y * 128, n0 = blockIdx.x * 128;
    const float* Ap = A + (size_t)(n0 / grpN) * grpStride;
    const uint32_t sbase = smem_u32(smem);

    const int wm = (wid >> 2) * 64;   // warp m offset in tile
    const int wn = (wid & 3) * 32;    // warp n offset in tile
    const int lg = lane >> 2;         // 0..7
    const int lc = lane & 3;          // 0..3

    float acc[4][4][4];
    #pragma unroll
    for (int mi = 0; mi < 4; mi++)
        #pragma unroll
        for (int ni = 0; ni < 4; ni++)
            #pragma unroll
            for (int r = 0; r < 4; r++) acc[mi][ni][r] = 0.f;

    // ---- stage chunk 0 ----
    {
        uint32_t dA = sbase, dB = sbase + STG_BYTES;
        #pragma unroll
        for (int i = 0; i < 4; i++) {
            int c = tid + i * 256;
            int row = c >> 3, q = (c & 7) * 4;
            cp_async16(dA + (row * ASTRIDE + q) * 4, Ap + (size_t)(m0 + row) * lda + q);
            cp_async16(dB + (row * ASTRIDE + q) * 4, B  + (size_t)(n0 + row) * ldb + q);
        }
        CP_COMMIT();
    }

    const int NC = K >> 5;
    for (int k = 0; k < NC; k++) {
        if (k + 1 < NC) {
            const int k0 = (k + 1) * 32;
            uint32_t dA = sbase + ((k + 1) & 1) * FULL_STAGE;
            uint32_t dB = dA + STG_BYTES;
            #pragma unroll
            for (int i = 0; i < 4; i++) {
                int c = tid + i * 256;
                int row = c >> 3, q = (c & 7) * 4;
                cp_async16(dA + (row * ASTRIDE + q) * 4, Ap + (size_t)(m0 + row) * lda + k0 + q);
                cp_async16(dB + (row * ASTRIDE + q) * 4, B  + (size_t)(n0 + row) * ldb + k0 + q);
            }
        }
        CP_COMMIT();
        CP_WAIT1();
        __syncthreads();

        const float* As = smem + (k & 1) * (2 * STG_FLOATS);
        const float* Bs = As + STG_FLOATS;

        #pragma unroll
        for (int kk = 0; kk < 32; kk += 8) {
            uint32_t a[4][4], b[4][2];
            #pragma unroll
            for (int mi = 0; mi < 4; mi++) {
                const int r = wm + mi * 16 + lg;
                a[mi][0] = f2tf32(As[r * ASTRIDE + kk + lc]);
                a[mi][1] = f2tf32(As[(r + 8) * ASTRIDE + kk + lc]);
                a[mi][2] = f2tf32(As[r * ASTRIDE + kk + 4 + lc]);
                a[mi][3] = f2tf32(As[(r + 8) * ASTRIDE + kk + 4 + lc]);
            }
            #pragma unroll
            for (int ni = 0; ni < 4; ni++) {
                const int n = wn + ni * 8 + lg;
                b[ni][0] = f2tf32(Bs[n * ASTRIDE + kk + lc]);
                b[ni][1] = f2tf32(Bs[n * ASTRIDE + kk + 4 + lc]);
            }
            #pragma unroll
            for (int mi = 0; mi < 4; mi++)
                #pragma unroll
                for (int ni = 0; ni < 4; ni++)
                    mma_tf32(acc[mi][ni], a[mi], b[ni]);
        }
        __syncthreads();
    }

    // epilogue
    #pragma unroll
    for (int mi = 0; mi < 4; mi++) {
        #pragma unroll
        for (int ni = 0; ni < 4; ni++) {
            const int r0 = m0 + wm + mi * 16 + lg;
            const int c0 = n0 + wn + ni * 8 + 2 * lc;
            *(float2*)(C + (size_t)r0 * ldc + c0) =
                make_float2(acc[mi][ni][0], acc[mi][ni][1]);
            *(float2*)(C + (size_t)(r0 + 8) * ldc + c0) =
                make_float2(acc[mi][ni][2], acc[mi][ni][3]);
        }
    }
}

// ---------------- q-latent RMS norm (row=1024, with weight) ----------------
__global__ void __launch_bounds__(256) qlat_norm_kernel(float* __restrict__ q,
                                                        const float* __restrict__ w)
{
    const int row = blockIdx.x;
    float* p = q + (size_t)row * QL;
    float4 v = *(float4*)(p + threadIdx.x * 4);
    float ssq = v.x * v.x + v.y * v.y + v.z * v.z + v.w * v.w;
    float tot = blk_sum_256(ssq);
    float inv = rsqrtf(tot * (1.f / QL) + EPSF);
    float4 wv = *(const float4*)(w + threadIdx.x * 4);
    v.x *= inv * wv.x; v.y *= inv * wv.y; v.z *= inv * wv.z; v.w *= inv * wv.w;
    *(float4*)(p + threadIdx.x * 4) = v;
}

// ---------------- per-head q norm + forward RoPE on last 64 dims ----------------
__global__ void __launch_bounds__(256) q_post_kernel(float* __restrict__ q,
                                                     const float* __restrict__ freqs)
{
    const int h = blockIdx.x, s = blockIdx.y, d = threadIdx.x;
    float* qp = q + (size_t)s * HD + h * DH;
    float v = qp[d];
    float tot = blk_sum_256(v * v);
    float nv = v * rsqrtf(tot * (1.f / DH) + EPSF);
    __shared__ float sh[DH];
    sh[d] = nv;
    __syncthreads();
    float outv = nv;
    if (d >= NOPE) {
        int p = (d - NOPE) >> 1;
        float f = freqs[s * (RR / 2) + p];
        float c = cosf(f), sn = sinf(f);
        outv = ((d & 1) == 0) ? sh[d] * c - sh[d + 1] * sn
                              : sh[d - 1] * sn + sh[d] * c;
    }
    qp[d] = outv;
}

// ---------------- kv RMS norm (weighted) + forward RoPE on last 64 dims ----------------
__global__ void __launch_bounds__(256) kv_post_kernel(float* __restrict__ kv,
                                                      const float* __restrict__ w,
                                                      const float* __restrict__ freqs)
{
    const int s = blockIdx.x, d = threadIdx.x;
    float* kp = kv + (size_t)s * DH;
    float v = kp[d];
    float tot = blk_sum_256(v * v);
    float nv = v * rsqrtf(tot * (1.f / DH) + EPSF) * w[d];
    __shared__ float sh[DH];
    sh[d] = nv;
    __syncthreads();
    float outv = nv;
    if (d >= NOPE) {
        int p = (d - NOPE) >> 1;
        float f = freqs[s * (RR / 2) + p];
        float c = cosf(f), sn = sinf(f);
        outv = ((d & 1) == 0) ? sh[d] * c - sh[d + 1] * sn
                              : sh[d - 1] * sn + sh[d] * c;
    }
    kp[d] = outv;
}

// ---------------- flash attention with sink + fused conj-RoPE epilogue ----------------
#define DP 260   // padded Q/K row (floats)
#define PSP 66   // padded P row
__global__ void __launch_bounds__(256) flash_kernel(
    const float* __restrict__ q, const float* __restrict__ kv,
    const float* __restrict__ freqs, const float* __restrict__ sink,
    float* __restrict__ o)
{
    extern __shared__ float sm[];
    float* Qs = sm;                 // 64 x DP
    float* Ks = sm + 64 * DP;       // 64 x DP (also serves as V)
    float* Ps = sm + 128 * DP;      // 64 x PSP

    const int h = blockIdx.y;
    const int q0 = (gridDim.x - 1 - blockIdx.x) * 64;  // heavy tiles first
    const int tid = threadIdx.x, ty = tid >> 4, tx = tid & 15;

    // load Q tile
    #pragma unroll
    for (int l = 0; l < 16; l++) {
        int lin = tid + l * 256;
        int r = lin >> 6, dq = (lin & 63) << 2;
        *(float4*)&Qs[r * DP + dq] =
            *(const float4*)(q + (size_t)(q0 + r) * HD + h * DH + dq);
    }

    float acc[4][16];
    #pragma unroll
    for (int i = 0; i < 4; i++)
        #pragma unroll
        for (int c = 0; c < 16; c++) acc[i][c] = 0.f;

    const float snk = sink[h];
    float m_i[4], l_i[4];
    #pragma unroll
    for (int i = 0; i < 4; i++) { m_i[i] = snk; l_i[i] = 1.f; }

    for (int t0 = 0; t0 <= q0; t0 += 64) {
        __syncthreads();  // Qs ready / previous PV finished with Ks
        #pragma unroll
        for (int l = 0; l < 16; l++) {
            int lin = tid + l * 256;
            int r = lin >> 6, dq = (lin & 63) << 2;
            *(float4*)&Ks[r * DP + dq] =
                *(const float4*)(kv + (size_t)(t0 + r) * DH + dq);
        }
        __syncthreads();

        // scores: 4x4 per thread over D=256
        float sc[4][4];
        #pragma unroll
        for (int i = 0; i < 4; i++)
            #pragma unroll
            for (int j = 0; j < 4; j++) sc[i][j] = 0.f;

        #pragma unroll 2
        for (int d4 = 0; d4 < DH; d4 += 4) {
            float4 qa[4], kb[4];
            #pragma unroll
            for (int i = 0; i < 4; i++) qa[i] = *(const float4*)&Qs[(ty * 4 + i) * DP + d4];
            #pragma unroll
            for (int j = 0; j < 4; j++) kb[j] = *(const float4*)&Ks[(tx * 4 + j) * DP + d4];
            #pragma unroll
            for (int i = 0; i < 4; i++)
                #pragma unroll
                for (int j = 0; j < 4; j++)
                    sc[i][j] += qa[i].x * kb[j].x + qa[i].y * kb[j].y
                              + qa[i].z * kb[j].z + qa[i].w * kb[j].w;
        }

        const bool diag = (t0 == q0);
        #pragma unroll
        for (int i = 0; i < 4; i++)
            #pragma unroll
            for (int j = 0; j < 4; j++) {
                sc[i][j] *= SCALE_F;
                if (diag && (tx * 4 + j) > (ty * 4 + i)) sc[i][j] = -1e30f;
            }

        // online softmax per row (16 lanes share a row group)
        #pragma unroll
        for (int i = 0; i < 4; i++) {
            float mt = fmaxf(fmaxf(sc[i][0], sc[i][1]), fmaxf(sc[i][2], sc[i][3]));
            #pragma unroll
            for (int off = 8; off; off >>= 1)
                mt = fmaxf(mt, __shfl_xor_sync(0xffffffffu, mt, off));
            float mnew = fmaxf(m_i[i], mt);
            float alpha = __expf(m_i[i] - mnew);
            float rs = 0.f;
            #pragma unroll
            for (int j = 0; j < 4; j++) {
                sc[i][j] = __expf(sc[i][j] - mnew);
                rs += sc[i][j];
            }
            #pragma unroll
            for (int off = 8; off; off >>= 1)
                rs += __shfl_xor_sync(0xffffffffu, rs, off);
            l_i[i] = l_i[i] * alpha + rs;
            m_i[i] = mnew;
            #pragma unroll
            for (int c = 0; c < 16; c++) acc[i][c] *= alpha;
            #pragma unroll
            for (int j = 0; j < 4; j++)
                Ps[(ty * 4 + i) * PSP + tx * 4 + j] = sc[i][j];
        }
        __syncthreads();

        // O += P @ V  (V == Ks)
        #pragma unroll 2
        for (int t = 0; t < 64; t++) {
            float p[4];
            #pragma unroll
            for (int i = 0; i < 4; i++) p[i] = Ps[(ty * 4 + i) * PSP + t];
            #pragma unroll
            for (int jc = 0; jc < 4; jc++) {
                float4 vv = *(const float4*)&Ks[t * DP + jc * 64 + tx * 4];
                #pragma unroll
                for (int i = 0; i < 4; i++) {
                    acc[i][jc * 4 + 0] = fmaf(p[i], vv.x, acc[i][jc * 4 + 0]);
                    acc[i][jc * 4 + 1] = fmaf(p[i], vv.y, acc[i][jc * 4 + 1]);
                    acc[i][jc * 4 + 2] = fmaf(p[i], vv.z, acc[i][jc * 4 + 2]);
                    acc[i][jc * 4 + 3] = fmaf(p[i], vv.w, acc[i][jc * 4 + 3]);
                }
            }
        }
    }

    // epilogue: normalize by l, conj-RoPE last 64 dims, store
    #pragma unroll
    for (int i = 0; i < 4; i++) {
        int r = q0 + ty * 4 + i;
        float invl = 1.f / l_i[i];
        float* orow = o + (size_t)r * HD + h * DH;
        #pragma unroll
        for (int jc = 0; jc < 3; jc++) {
            float4 v = make_float4(acc[i][jc * 4 + 0] * invl, acc[i][jc * 4 + 1] * invl,
                                   acc[i][jc * 4 + 2] * invl, acc[i][jc * 4 + 3] * invl);
            *(float4*)(orow + jc * 64 + tx * 4) = v;
        }
        {
            float v0 = acc[i][12] * invl, v1 = acc[i][13] * invl;
            float v2 = acc[i][14] * invl, v3 = acc[i][15] * invl;
            float f0 = freqs[r * (RR / 2) + tx * 2];
            float f1 = freqs[r * (RR / 2) + tx * 2 + 1];
            float c0 = cosf(f0), s0 = sinf(f0), c1 = cosf(f1), s1 = sinf(f1);
            float4 v = make_float4(v0 * c0 + v1 * s0, -v0 * s0 + v1 * c0,
                                   v2 * c1 + v3 * s1, -v2 * s1 + v3 * c1);
            *(float4*)(orow + NOPE + tx * 4) = v;
        }
    }
}

// ---------------- launch ----------------
extern "C" void kernel_launch(void* const* d_in, const int* in_sizes, int n_in,
                              void* d_out, int out_size)
{
    const float* x     = (const float*)d_in[0];
    const float* freqs = (const float*)d_in[1];
    const float* wq_a  = (const float*)d_in[2];
    const float* qnw   = (const float*)d_in[3];
    const float* wq_b  = (const float*)d_in[4];
    const float* wkv   = (const float*)d_in[5];
    const float* kvnw  = (const float*)d_in[6];
    const float* wo_a  = (const float*)d_in[7];
    const float* wo_b  = (const float*)d_in[8];
    const float* sink  = (const float*)d_in[9];
    float* out = (float*)d_out;
    (void)in_sizes; (void)n_in; (void)out_size;

    float *qlat, *qbuf, *kvbuf, *obuf, *orbuf;
    cudaGetSymbolAddress((void**)&qlat,  g_qlat);
    cudaGetSymbolAddress((void**)&qbuf,  g_q);
    cudaGetSymbolAddress((void**)&kvbuf, g_kv);
    cudaGetSymbolAddress((void**)&obuf,  g_o);
    cudaGetSymbolAddress((void**)&orbuf, g_or);

    const int BIGN = 1 << 30;
    cudaFuncSetAttribute(gemm_mma_kernel, cudaFuncAttributeMaxDynamicSharedMemorySize, GEMM_SMEM);

    // 1) q_lat = x @ wq_a^T ; RMS norm
    gemm_mma_kernel<<<dim3(QL / 128, S_LEN / 128), 256, GEMM_SMEM>>>(
        x, wq_a, qlat, HID, HID, HID, QL, BIGN, 0);
    qlat_norm_kernel<<<S_LEN, 256>>>(qlat, qnw);

    // 2) q = q_lat @ wq_b^T ; per-head norm + RoPE
    gemm_mma_kernel<<<dim3(HD / 128, S_LEN / 128), 256, GEMM_SMEM>>>(
        qlat, wq_b, qbuf, QL, QL, QL, HD, BIGN, 0);
    q_post_kernel<<<dim3(NH, S_LEN), 256>>>(qbuf, freqs);

    // 3) kv = rms(x @ wkv^T) ; RoPE
    gemm_mma_kernel<<<dim3(DH / 128, S_LEN / 128), 256, GEMM_SMEM>>>(
        x, wkv, kvbuf, HID, HID, HID, DH, BIGN, 0);
    kv_post_kernel<<<S_LEN, 256>>>(kvbuf, kvnw, freqs);

    // 4) flash attention with sink + conj-RoPE epilogue
    size_t smem = (size_t)(2 * 64 * DP + 64 * PSP) * sizeof(float);
    cudaFuncSetAttribute(flash_kernel, cudaFuncAttributeMaxDynamicSharedMemorySize, (int)smem);
    flash_kernel<<<dim3(S_LEN / 64, NH), 256, smem>>>(qbuf, kvbuf, freqs, sink, obuf);

    // 5) grouped o_r GEMM (block-diagonal wo_a): A offset = group * (HPG*D)
    gemm_mma_kernel<<<dim3(GO / 128, S_LEN / 128), 256, GEMM_SMEM>>>(
        obuf, wo_a, orbuf, NG * DH, HD, NG * DH, GO, ORANK, NG * DH);

    // 6) out = o_r @ wo_b^T
    gemm_mma_kernel<<<dim3(HID / 128, S_LEN / 128), 256, GEMM_SMEM>>>(
        orbuf, wo_b, out, GO, GO, GO, HID, BIGN, 0);
}

// round 7
// speedup vs baseline: 1.4578x; 1.4578x over previous
#include <cuda_runtime.h>
#include <cuda_bf16.h>
#include <math.h>
#include <stdint.h>

// Problem constants
#define S_LEN 2048
#define HID   2048
#define NH    16
#define DH    256
#define RR    64
#define NOPE  192
#define QL    1024
#define ORANK 512
#define NG    4
#define HD    (NH*DH)    // 4096
#define GO    (NG*ORANK) // 2048
#define EPSF  1e-6f
#define SCALE_F 0.0625f  // 256^-0.5

// ---------------- scratch (static device globals; no allocation) ----------------
__device__ float g_qlat[S_LEN * QL];    // 8 MB
__device__ float g_q   [S_LEN * HD];    // 32 MB
__device__ float g_kv  [S_LEN * DH];    // 2 MB
__device__ float g_o   [S_LEN * HD];    // 32 MB
__device__ float g_or  [S_LEN * GO];    // 16 MB

// =================== helpers ===================
__device__ __forceinline__ void mma_bf16(float* d, const uint32_t* a, const uint32_t* b) {
    asm volatile(
        "mma.sync.aligned.m16n8k16.row.col.f32.bf16.bf16.f32 "
        "{%0,%1,%2,%3}, {%4,%5,%6,%7}, {%8,%9}, {%0,%1,%2,%3};"
        : "+f"(d[0]), "+f"(d[1]), "+f"(d[2]), "+f"(d[3])
        : "r"(a[0]), "r"(a[1]), "r"(a[2]), "r"(a[3]), "r"(b[0]), "r"(b[1]));
}

__device__ __forceinline__ uint32_t pack_bf16(__nv_bfloat16 a, __nv_bfloat16 b) {
    __nv_bfloat162 t;
    t.x = a; t.y = b;
    return *reinterpret_cast<uint32_t*>(&t);
}
// split x,y into hi/lo bf16x2 words
__device__ __forceinline__ void split2(float x, float y, uint32_t& hi, uint32_t& lo) {
    __nv_bfloat16 hx = __float2bfloat16(x);
    __nv_bfloat16 hy = __float2bfloat16(y);
    __nv_bfloat16 lx = __float2bfloat16(x - __bfloat162float(hx));
    __nv_bfloat16 ly = __float2bfloat16(y - __bfloat162float(hy));
    hi = pack_bf16(hx, hy);
    lo = pack_bf16(lx, ly);
}

// ---------------- block reduction (256 threads) ----------------
__device__ __forceinline__ float blk_sum_256(float v) {
    __shared__ float red[8];
    #pragma unroll
    for (int o = 16; o; o >>= 1) v += __shfl_xor_sync(0xffffffffu, v, o);
    if ((threadIdx.x & 31) == 0) red[threadIdx.x >> 5] = v;
    __syncthreads();
    float t = 0.f;
    #pragma unroll
    for (int i = 0; i < 8; i++) t += red[i];
    return t;
}

// =================== bf16x3 mma GEMM: C[M,N] = A[M,K] * B[N,K]^T ===================
// CTA tile 128x128, K-chunk 32, 512 threads (16 warps, 4x4), warp tile 32x32.
// SMEM: per stage 4 planes (Ah, Al, Bh, Bl), each 128 rows x 40 uint16 (80B stride).
#define RSTR 40                       // uint16 per row (32 data + 8 pad)
#define PLANE (128 * RSTR)            // 5120 uint16 = 10240 B
#define STAGE_U16 (4 * PLANE)         // 20480 uint16 = 40960 B
#define GEMM_SMEM (2 * STAGE_U16 * 2) // 81920 B

__global__ void __launch_bounds__(512, 1) gemm_bf16x3_kernel(
    const float* __restrict__ A, const float* __restrict__ B, float* __restrict__ C,
    int K, int lda, int ldb, int ldc, int grpN, int grpStride)
{
    extern __shared__ __align__(16) uint16_t smem[];
    const int tid = threadIdx.x, lane = tid & 31, wid = tid >> 5;
    const int m0 = blockIdx.y * 128, n0 = blockIdx.x * 128;
    const float* Ap = A + (size_t)(n0 / grpN) * grpStride;

    const int wm = (wid >> 2) * 32;   // warp m offset
    const int wn = (wid & 3) * 32;    // warp n offset
    const int lg = lane >> 2;         // 0..7
    const int lc = lane & 3;          // 0..3

    // per-thread staging: 2 float4 from A, 2 from B per chunk
    const int r0 = tid >> 3, r1 = (tid + 512) >> 3;      // rows 0..127
    const int q0 = (tid & 7) * 4, q1 = ((tid + 512) & 7) * 4;  // k offset

    float acc[2][4][4];
    #pragma unroll
    for (int mi = 0; mi < 2; mi++)
        #pragma unroll
        for (int ni = 0; ni < 4; ni++)
            #pragma unroll
            for (int r = 0; r < 4; r++) acc[mi][ni][r] = 0.f;

    float4 va0, va1, vb0, vb1;

    // load chunk 0
    va0 = *(const float4*)(Ap + (size_t)(m0 + r0) * lda + q0);
    va1 = *(const float4*)(Ap + (size_t)(m0 + r1) * lda + q1);
    vb0 = *(const float4*)(B  + (size_t)(n0 + r0) * ldb + q0);
    vb1 = *(const float4*)(B  + (size_t)(n0 + r1) * ldb + q1);

    const int NC = K >> 5;
    for (int k = 0; k < NC; k++) {
        // convert + store current regs into stage k&1
        {
            uint16_t* st = smem + (k & 1) * STAGE_U16;
            uint32_t h01, l01, h23, l23;
            split2(va0.x, va0.y, h01, l01); split2(va0.z, va0.w, h23, l23);
            *(uint2*)&st[r0 * RSTR + q0] = make_uint2(h01, h23);
            *(uint2*)&st[PLANE + r0 * RSTR + q0] = make_uint2(l01, l23);
            split2(va1.x, va1.y, h01, l01); split2(va1.z, va1.w, h23, l23);
            *(uint2*)&st[r1 * RSTR + q1] = make_uint2(h01, h23);
            *(uint2*)&st[PLANE + r1 * RSTR + q1] = make_uint2(l01, l23);
            split2(vb0.x, vb0.y, h01, l01); split2(vb0.z, vb0.w, h23, l23);
            *(uint2*)&st[2 * PLANE + r0 * RSTR + q0] = make_uint2(h01, h23);
            *(uint2*)&st[3 * PLANE + r0 * RSTR + q0] = make_uint2(l01, l23);
            split2(vb1.x, vb1.y, h01, l01); split2(vb1.z, vb1.w, h23, l23);
            *(uint2*)&st[2 * PLANE + r1 * RSTR + q1] = make_uint2(h01, h23);
            *(uint2*)&st[3 * PLANE + r1 * RSTR + q1] = make_uint2(l01, l23);
        }
        __syncthreads();

        // issue global loads for next chunk
        if (k + 1 < NC) {
            const int kc = (k + 1) * 32;
            va0 = *(const float4*)(Ap + (size_t)(m0 + r0) * lda + kc + q0);
            va1 = *(const float4*)(Ap + (size_t)(m0 + r1) * lda + kc + q1);
            vb0 = *(const float4*)(B  + (size_t)(n0 + r0) * ldb + kc + q0);
            vb1 = *(const float4*)(B  + (size_t)(n0 + r1) * ldb + kc + q1);
        }

        // MMA on stage k&1
        const uint16_t* Ah = smem + (k & 1) * STAGE_U16;
        const uint16_t* Al = Ah + PLANE;
        const uint16_t* Bh = Ah + 2 * PLANE;
        const uint16_t* Bl = Ah + 3 * PLANE;

        #pragma unroll
        for (int kk = 0; kk < 32; kk += 16) {
            uint32_t ah[2][4], al[2][4], bh[4][2], bl[4][2];
            #pragma unroll
            for (int mi = 0; mi < 2; mi++) {
                const int rr = (wm + mi * 16 + lg) * RSTR + kk + lc * 2;
                ah[mi][0] = *(const uint32_t*)&Ah[rr];
                ah[mi][1] = *(const uint32_t*)&Ah[rr + 8 * RSTR];
                ah[mi][2] = *(const uint32_t*)&Ah[rr + 8];
                ah[mi][3] = *(const uint32_t*)&Ah[rr + 8 * RSTR + 8];
                al[mi][0] = *(const uint32_t*)&Al[rr];
                al[mi][1] = *(const uint32_t*)&Al[rr + 8 * RSTR];
                al[mi][2] = *(const uint32_t*)&Al[rr + 8];
                al[mi][3] = *(const uint32_t*)&Al[rr + 8 * RSTR + 8];
            }
            #pragma unroll
            for (int ni = 0; ni < 4; ni++) {
                const int rr = (wn + ni * 8 + lg) * RSTR + kk + lc * 2;
                bh[ni][0] = *(const uint32_t*)&Bh[rr];
                bh[ni][1] = *(const uint32_t*)&Bh[rr + 8];
                bl[ni][0] = *(const uint32_t*)&Bl[rr];
                bl[ni][1] = *(const uint32_t*)&Bl[rr + 8];
            }
            #pragma unroll
            for (int mi = 0; mi < 2; mi++)
                #pragma unroll
                for (int ni = 0; ni < 4; ni++) {
                    mma_bf16(acc[mi][ni], ah[mi], bh[ni]);
                    mma_bf16(acc[mi][ni], ah[mi], bl[ni]);
                    mma_bf16(acc[mi][ni], al[mi], bh[ni]);
                }
        }
        __syncthreads();
    }

    // epilogue
    #pragma unroll
    for (int mi = 0; mi < 2; mi++) {
        #pragma unroll
        for (int ni = 0; ni < 4; ni++) {
            const int rr = m0 + wm + mi * 16 + lg;
            const int cc = n0 + wn + ni * 8 + 2 * lc;
            *(float2*)(C + (size_t)rr * ldc + cc) =
                make_float2(acc[mi][ni][0], acc[mi][ni][1]);
            *(float2*)(C + (size_t)(rr + 8) * ldc + cc) =
                make_float2(acc[mi][ni][2], acc[mi][ni][3]);
        }
    }
}

// ---------------- q-latent RMS norm (row=1024, with weight) ----------------
__global__ void __launch_bounds__(256) qlat_norm_kernel(float* __restrict__ q,
                                                        const float* __restrict__ w)
{
    const int row = blockIdx.x;
    float* p = q + (size_t)row * QL;
    float4 v = *(float4*)(p + threadIdx.x * 4);
    float ssq = v.x * v.x + v.y * v.y + v.z * v.z + v.w * v.w;
    float tot = blk_sum_256(ssq);
    float inv = rsqrtf(tot * (1.f / QL) + EPSF);
    float4 wv = *(const float4*)(w + threadIdx.x * 4);
    v.x *= inv * wv.x; v.y *= inv * wv.y; v.z *= inv * wv.z; v.w *= inv * wv.w;
    *(float4*)(p + threadIdx.x * 4) = v;
}

// ---------------- per-head q norm + forward RoPE on last 64 dims ----------------
__global__ void __launch_bounds__(256) q_post_kernel(float* __restrict__ q,
                                                     const float* __restrict__ freqs)
{
    const int h = blockIdx.x, s = blockIdx.y, d = threadIdx.x;
    float* qp = q + (size_t)s * HD + h * DH;
    float v = qp[d];
    float tot = blk_sum_256(v * v);
    float nv = v * rsqrtf(tot * (1.f / DH) + EPSF);
    __shared__ float sh[DH];
    sh[d] = nv;
    __syncthreads();
    float outv = nv;
    if (d >= NOPE) {
        int p = (d - NOPE) >> 1;
        float f = freqs[s * (RR / 2) + p];
        float c = cosf(f), sn = sinf(f);
        outv = ((d & 1) == 0) ? sh[d] * c - sh[d + 1] * sn
                              : sh[d - 1] * sn + sh[d] * c;
    }
    qp[d] = outv;
}

// ---------------- kv RMS norm (weighted) + forward RoPE on last 64 dims ----------------
__global__ void __launch_bounds__(256) kv_post_kernel(float* __restrict__ kv,
                                                      const float* __restrict__ w,
                                                      const float* __restrict__ freqs)
{
    const int s = blockIdx.x, d = threadIdx.x;
    float* kp = kv + (size_t)s * DH;
    float v = kp[d];
    float tot = blk_sum_256(v * v);
    float nv = v * rsqrtf(tot * (1.f / DH) + EPSF) * w[d];
    __shared__ float sh[DH];
    sh[d] = nv;
    __syncthreads();
    float outv = nv;
    if (d >= NOPE) {
        int p = (d - NOPE) >> 1;
        float f = freqs[s * (RR / 2) + p];
        float c = cosf(f), sn = sinf(f);
        outv = ((d & 1) == 0) ? sh[d] * c - sh[d + 1] * sn
                              : sh[d - 1] * sn + sh[d] * c;
    }
    kp[d] = outv;
}

// ---------------- flash attention with sink + fused conj-RoPE epilogue ----------------
#define DP 260   // padded Q/K row (floats)
#define PSP 66   // padded P row
__global__ void __launch_bounds__(256) flash_kernel(
    const float* __restrict__ q, const float* __restrict__ kv,
    const float* __restrict__ freqs, const float* __restrict__ sink,
    float* __restrict__ o)
{
    extern __shared__ float sm[];
    float* Qs = sm;                 // 64 x DP
    float* Ks = sm + 64 * DP;       // 64 x DP (also serves as V)
    float* Ps = sm + 128 * DP;      // 64 x PSP

    const int h = blockIdx.y;
    const int q0 = (gridDim.x - 1 - blockIdx.x) * 64;  // heavy tiles first
    const int tid = threadIdx.x, ty = tid >> 4, tx = tid & 15;

    // load Q tile
    #pragma unroll
    for (int l = 0; l < 16; l++) {
        int lin = tid + l * 256;
        int r = lin >> 6, dq = (lin & 63) << 2;
        *(float4*)&Qs[r * DP + dq] =
            *(const float4*)(q + (size_t)(q0 + r) * HD + h * DH + dq);
    }

    float acc[4][16];
    #pragma unroll
    for (int i = 0; i < 4; i++)
        #pragma unroll
        for (int c = 0; c < 16; c++) acc[i][c] = 0.f;

    const float snk = sink[h];
    float m_i[4], l_i[4];
    #pragma unroll
    for (int i = 0; i < 4; i++) { m_i[i] = snk; l_i[i] = 1.f; }

    for (int t0 = 0; t0 <= q0; t0 += 64) {
        __syncthreads();  // Qs ready / previous PV finished with Ks
        #pragma unroll
        for (int l = 0; l < 16; l++) {
            int lin = tid + l * 256;
            int r = lin >> 6, dq = (lin & 63) << 2;
            *(float4*)&Ks[r * DP + dq] =
                *(const float4*)(kv + (size_t)(t0 + r) * DH + dq);
        }
        __syncthreads();

        // scores: 4x4 per thread over D=256
        float sc[4][4];
        #pragma unroll
        for (int i = 0; i < 4; i++)
            #pragma unroll
            for (int j = 0; j < 4; j++) sc[i][j] = 0.f;

        #pragma unroll 2
        for (int d4 = 0; d4 < DH; d4 += 4) {
            float4 qa[4], kb[4];
            #pragma unroll
            for (int i = 0; i < 4; i++) qa[i] = *(const float4*)&Qs[(ty * 4 + i) * DP + d4];
            #pragma unroll
            for (int j = 0; j < 4; j++) kb[j] = *(const float4*)&Ks[(tx * 4 + j) * DP + d4];
            #pragma unroll
            for (int i = 0; i < 4; i++)
                #pragma unroll
                for (int j = 0; j < 4; j++)
                    sc[i][j] += qa[i].x * kb[j].x + qa[i].y * kb[j].y
                              + qa[i].z * kb[j].z + qa[i].w * kb[j].w;
        }

        const bool diag = (t0 == q0);
        #pragma unroll
        for (int i = 0; i < 4; i++)
            #pragma unroll
            for (int j = 0; j < 4; j++) {
                sc[i][j] *= SCALE_F;
                if (diag && (tx * 4 + j) > (ty * 4 + i)) sc[i][j] = -1e30f;
            }

        // online softmax per row (16 lanes share a row group)
        #pragma unroll
        for (int i = 0; i < 4; i++) {
            float mt = fmaxf(fmaxf(sc[i][0], sc[i][1]), fmaxf(sc[i][2], sc[i][3]));
            #pragma unroll
            for (int off = 8; off; off >>= 1)
                mt = fmaxf(mt, __shfl_xor_sync(0xffffffffu, mt, off));
            float mnew = fmaxf(m_i[i], mt);
            float alpha = __expf(m_i[i] - mnew);
            float rs = 0.f;
            #pragma unroll
            for (int j = 0; j < 4; j++) {
                sc[i][j] = __expf(sc[i][j] - mnew);
                rs += sc[i][j];
            }
            #pragma unroll
            for (int off = 8; off; off >>= 1)
                rs += __shfl_xor_sync(0xffffffffu, rs, off);
            l_i[i] = l_i[i] * alpha + rs;
            m_i[i] = mnew;
            #pragma unroll
            for (int c = 0; c < 16; c++) acc[i][c] *= alpha;
            #pragma unroll
            for (int j = 0; j < 4; j++)
                Ps[(ty * 4 + i) * PSP + tx * 4 + j] = sc[i][j];
        }
        __syncthreads();

        // O += P @ V  (V == Ks)
        #pragma unroll 2
        for (int t = 0; t < 64; t++) {
            float p[4];
            #pragma unroll
            for (int i = 0; i < 4; i++) p[i] = Ps[(ty * 4 + i) * PSP + t];
            #pragma unroll
            for (int jc = 0; jc < 4; jc++) {
                float4 vv = *(const float4*)&Ks[t * DP + jc * 64 + tx * 4];
                #pragma unroll
                for (int i = 0; i < 4; i++) {
                    acc[i][jc * 4 + 0] = fmaf(p[i], vv.x, acc[i][jc * 4 + 0]);
                    acc[i][jc * 4 + 1] = fmaf(p[i], vv.y, acc[i][jc * 4 + 1]);
                    acc[i][jc * 4 + 2] = fmaf(p[i], vv.z, acc[i][jc * 4 + 2]);
                    acc[i][jc * 4 + 3] = fmaf(p[i], vv.w, acc[i][jc * 4 + 3]);
                }
            }
        }
    }

    // epilogue: normalize by l, conj-RoPE last 64 dims, store
    #pragma unroll
    for (int i = 0; i < 4; i++) {
        int r = q0 + ty * 4 + i;
        float invl = 1.f / l_i[i];
        float* orow = o + (size_t)r * HD + h * DH;
        #pragma unroll
        for (int jc = 0; jc < 3; jc++) {
            float4 v = make_float4(acc[i][jc * 4 + 0] * invl, acc[i][jc * 4 + 1] * invl,
                                   acc[i][jc * 4 + 2] * invl, acc[i][jc * 4 + 3] * invl);
            *(float4*)(orow + jc * 64 + tx * 4) = v;
        }
        {
            float v0 = acc[i][12] * invl, v1 = acc[i][13] * invl;
            float v2 = acc[i][14] * invl, v3 = acc[i][15] * invl;
            float f0 = freqs[r * (RR / 2) + tx * 2];
            float f1 = freqs[r * (RR / 2) + tx * 2 + 1];
            float c0 = cosf(f0), s0 = sinf(f0), c1 = cosf(f1), s1 = sinf(f1);
            float4 v = make_float4(v0 * c0 + v1 * s0, -v0 * s0 + v1 * c0,
                                   v2 * c1 + v3 * s1, -v2 * s1 + v3 * c1);
            *(float4*)(orow + NOPE + tx * 4) = v;
        }
    }
}

// ---------------- launch ----------------
extern "C" void kernel_launch(void* const* d_in, const int* in_sizes, int n_in,
                              void* d_out, int out_size)
{
    const float* x     = (const float*)d_in[0];
    const float* freqs = (const float*)d_in[1];
    const float* wq_a  = (const float*)d_in[2];
    const float* qnw   = (const float*)d_in[3];
    const float* wq_b  = (const float*)d_in[4];
    const float* wkv   = (const float*)d_in[5];
    const float* kvnw  = (const float*)d_in[6];
    const float* wo_a  = (const float*)d_in[7];
    const float* wo_b  = (const float*)d_in[8];
    const float* sink  = (const float*)d_in[9];
    float* out = (float*)d_out;
    (void)in_sizes; (void)n_in; (void)out_size;

    float *qlat, *qbuf, *kvbuf, *obuf, *orbuf;
    cudaGetSymbolAddress((void**)&qlat,  g_qlat);
    cudaGetSymbolAddress((void**)&qbuf,  g_q);
    cudaGetSymbolAddress((void**)&kvbuf, g_kv);
    cudaGetSymbolAddress((void**)&obuf,  g_o);
    cudaGetSymbolAddress((void**)&orbuf, g_or);

    const int BIGN = 1 << 30;
    cudaFuncSetAttribute(gemm_bf16x3_kernel, cudaFuncAttributeMaxDynamicSharedMemorySize, GEMM_SMEM);

    // 1) q_lat = x @ wq_a^T ; RMS norm
    gemm_bf16x3_kernel<<<dim3(QL / 128, S_LEN / 128), 512, GEMM_SMEM>>>(
        x, wq_a, qlat, HID, HID, HID, QL, BIGN, 0);
    qlat_norm_kernel<<<S_LEN, 256>>>(qlat, qnw);

    // 2) q = q_lat @ wq_b^T ; per-head norm + RoPE
    gemm_bf16x3_kernel<<<dim3(HD / 128, S_LEN / 128), 512, GEMM_SMEM>>>(
        qlat, wq_b, qbuf, QL, QL, QL, HD, BIGN, 0);
    q_post_kernel<<<dim3(NH, S_LEN), 256>>>(qbuf, freqs);

    // 3) kv = rms(x @ wkv^T) ; RoPE
    gemm_bf16x3_kernel<<<dim3(DH / 128, S_LEN / 128), 512, GEMM_SMEM>>>(
        x, wkv, kvbuf, HID, HID, HID, DH, BIGN, 0);
    kv_post_kernel<<<S_LEN, 256>>>(kvbuf, kvnw, freqs);

    // 4) flash attention with sink + conj-RoPE epilogue
    size_t smem = (size_t)(2 * 64 * DP + 64 * PSP) * sizeof(float);
    cudaFuncSetAttribute(flash_kernel, cudaFuncAttributeMaxDynamicSharedMemorySize, (int)smem);
    flash_kernel<<<dim3(S_LEN / 64, NH), 256, smem>>>(qbuf, kvbuf, freqs, sink, obuf);

    // 5) grouped o_r GEMM (block-diagonal wo_a): A offset = group * (HPG*D)
    gemm_bf16x3_kernel<<<dim3(GO / 128, S_LEN / 128), 512, GEMM_SMEM>>>(
        obuf, wo_a, orbuf, NG * DH, HD, NG * DH, GO, ORANK, NG * DH);

    // 6) out = o_r @ wo_b^T
    gemm_bf16x3_kernel<<<dim3(HID / 128, S_LEN / 128), 512, GEMM_SMEM>>>(
        orbuf, wo_b, out, GO, GO, GO, HID, BIGN, 0);
}

// round 13
// speedup vs baseline: 3.0255x; 2.0753x over previous
#include <cuda_runtime.h>
#include <cuda_bf16.h>
#include <math.h>
#include <stdint.h>

// Problem constants
#define S_LEN 2048
#define HID   2048
#define NH    16
#define DH    256
#define RR    64
#define NOPE  192
#define QL    1024
#define ORANK 512
#define NG    4
#define HD    (NH*DH)    // 4096
#define GO    (NG*ORANK) // 2048
#define EPSF  1e-6f
#define SCALE_F 0.0625f  // 256^-0.5

// ---------------- scratch (static device globals; no allocation) ----------------
__device__ float g_qlat[S_LEN * QL];    // 8 MB
__device__ float g_q   [S_LEN * HD];    // 32 MB
__device__ float g_kv  [S_LEN * DH];    // 2 MB
__device__ float g_o   [S_LEN * HD];    // 32 MB
__device__ float g_or  [S_LEN * GO];    // 16 MB
// bf16 hi/lo planes for flash attention
__device__ uint16_t g_qh [S_LEN * HD];
__device__ uint16_t g_qlo[S_LEN * HD];
__device__ uint16_t g_kvh[S_LEN * DH];
__device__ uint16_t g_kvl[S_LEN * DH];
__device__ uint16_t g_vth[DH * S_LEN];
__device__ uint16_t g_vtl[DH * S_LEN];

// =================== helpers ===================
__device__ __forceinline__ void mma_bf16(float* d, const uint32_t* a, const uint32_t* b) {
    asm volatile(
        "mma.sync.aligned.m16n8k16.row.col.f32.bf16.bf16.f32 "
        "{%0,%1,%2,%3}, {%4,%5,%6,%7}, {%8,%9}, {%0,%1,%2,%3};"
        : "+f"(d[0]), "+f"(d[1]), "+f"(d[2]), "+f"(d[3])
        : "r"(a[0]), "r"(a[1]), "r"(a[2]), "r"(a[3]), "r"(b[0]), "r"(b[1]));
}
__device__ __forceinline__ uint32_t pack_bf16(__nv_bfloat16 a, __nv_bfloat16 b) {
    __nv_bfloat162 t;
    t.x = a; t.y = b;
    return *reinterpret_cast<uint32_t*>(&t);
}
__device__ __forceinline__ void split2(float x, float y, uint32_t& hi, uint32_t& lo) {
    __nv_bfloat16 hx = __float2bfloat16(x);
    __nv_bfloat16 hy = __float2bfloat16(y);
    __nv_bfloat16 lx = __float2bfloat16(x - __bfloat162float(hx));
    __nv_bfloat16 ly = __float2bfloat16(y - __bfloat162float(hy));
    hi = pack_bf16(hx, hy);
    lo = pack_bf16(lx, ly);
}
__device__ __forceinline__ void split1(float x, uint16_t& hi, uint16_t& lo) {
    __nv_bfloat16 hx = __float2bfloat16(x);
    __nv_bfloat16 lx = __float2bfloat16(x - __bfloat162float(hx));
    hi = *reinterpret_cast<uint16_t*>(&hx);
    lo = *reinterpret_cast<uint16_t*>(&lx);
}

// ---------------- block reduction (256 threads) ----------------
__device__ __forceinline__ float blk_sum_256(float v) {
    __shared__ float red[8];
    #pragma unroll
    for (int o = 16; o; o >>= 1) v += __shfl_xor_sync(0xffffffffu, v, o);
    if ((threadIdx.x & 31) == 0) red[threadIdx.x >> 5] = v;
    __syncthreads();
    float t = 0.f;
    #pragma unroll
    for (int i = 0; i < 8; i++) t += red[i];
    return t;
}

// =================== bf16x3 mma GEMM: C[M,N] = A[M,K] * B[N,K]^T ===================
#define RSTR 40
#define PLANE (128 * RSTR)
#define STAGE_U16 (4 * PLANE)
#define GEMM_SMEM (2 * STAGE_U16 * 2)

__global__ void __launch_bounds__(512, 1) gemm_bf16x3_kernel(
    const float* __restrict__ A, const float* __restrict__ B, float* __restrict__ C,
    int K, int lda, int ldb, int ldc, int grpN, int grpStride)
{
    extern __shared__ __align__(16) uint16_t smem[];
    const int tid = threadIdx.x, lane = tid & 31, wid = tid >> 5;
    const int m0 = blockIdx.y * 128, n0 = blockIdx.x * 128;
    const float* Ap = A + (size_t)(n0 / grpN) * grpStride;

    const int wm = (wid >> 2) * 32;
    const int wn = (wid & 3) * 32;
    const int lg = lane >> 2;
    const int lc = lane & 3;

    const int r0 = tid >> 3, r1 = (tid + 512) >> 3;
    const int q0 = (tid & 7) * 4, q1 = ((tid + 512) & 7) * 4;

    float acc[2][4][4];
    #pragma unroll
    for (int mi = 0; mi < 2; mi++)
        #pragma unroll
        for (int ni = 0; ni < 4; ni++)
            #pragma unroll
            for (int r = 0; r < 4; r++) acc[mi][ni][r] = 0.f;

    float4 va0, va1, vb0, vb1;
    va0 = *(const float4*)(Ap + (size_t)(m0 + r0) * lda + q0);
    va1 = *(const float4*)(Ap + (size_t)(m0 + r1) * lda + q1);
    vb0 = *(const float4*)(B  + (size_t)(n0 + r0) * ldb + q0);
    vb1 = *(const float4*)(B  + (size_t)(n0 + r1) * ldb + q1);

    const int NC = K >> 5;
    for (int k = 0; k < NC; k++) {
        {
            uint16_t* st = smem + (k & 1) * STAGE_U16;
            uint32_t h01, l01, h23, l23;
            split2(va0.x, va0.y, h01, l01); split2(va0.z, va0.w, h23, l23);
            *(uint2*)&st[r0 * RSTR + q0] = make_uint2(h01, h23);
            *(uint2*)&st[PLANE + r0 * RSTR + q0] = make_uint2(l01, l23);
            split2(va1.x, va1.y, h01, l01); split2(va1.z, va1.w, h23, l23);
            *(uint2*)&st[r1 * RSTR + q1] = make_uint2(h01, h23);
            *(uint2*)&st[PLANE + r1 * RSTR + q1] = make_uint2(l01, l23);
            split2(vb0.x, vb0.y, h01, l01); split2(vb0.z, vb0.w, h23, l23);
            *(uint2*)&st[2 * PLANE + r0 * RSTR + q0] = make_uint2(h01, h23);
            *(uint2*)&st[3 * PLANE + r0 * RSTR + q0] = make_uint2(l01, l23);
            split2(vb1.x, vb1.y, h01, l01); split2(vb1.z, vb1.w, h23, l23);
            *(uint2*)&st[2 * PLANE + r1 * RSTR + q1] = make_uint2(h01, h23);
            *(uint2*)&st[3 * PLANE + r1 * RSTR + q1] = make_uint2(l01, l23);
        }
        __syncthreads();

        if (k + 1 < NC) {
            const int kc = (k + 1) * 32;
            va0 = *(const float4*)(Ap + (size_t)(m0 + r0) * lda + kc + q0);
            va1 = *(const float4*)(Ap + (size_t)(m0 + r1) * lda + kc + q1);
            vb0 = *(const float4*)(B  + (size_t)(n0 + r0) * ldb + kc + q0);
            vb1 = *(const float4*)(B  + (size_t)(n0 + r1) * ldb + kc + q1);
        }

        const uint16_t* Ah = smem + (k & 1) * STAGE_U16;
        const uint16_t* Al = Ah + PLANE;
        const uint16_t* Bh = Ah + 2 * PLANE;
        const uint16_t* Bl = Ah + 3 * PLANE;

        #pragma unroll
        for (int kk = 0; kk < 32; kk += 16) {
            uint32_t ah[2][4], al[2][4], bh[4][2], bl[4][2];
            #pragma unroll
            for (int mi = 0; mi < 2; mi++) {
                const int rr = (wm + mi * 16 + lg) * RSTR + kk + lc * 2;
                ah[mi][0] = *(const uint32_t*)&Ah[rr];
                ah[mi][1] = *(const uint32_t*)&Ah[rr + 8 * RSTR];
                ah[mi][2] = *(const uint32_t*)&Ah[rr + 8];
                ah[mi][3] = *(const uint32_t*)&Ah[rr + 8 * RSTR + 8];
                al[mi][0] = *(const uint32_t*)&Al[rr];
                al[mi][1] = *(const uint32_t*)&Al[rr + 8 * RSTR];
                al[mi][2] = *(const uint32_t*)&Al[rr + 8];
                al[mi][3] = *(const uint32_t*)&Al[rr + 8 * RSTR + 8];
            }
            #pragma unroll
            for (int ni = 0; ni < 4; ni++) {
                const int rr = (wn + ni * 8 + lg) * RSTR + kk + lc * 2;
                bh[ni][0] = *(const uint32_t*)&Bh[rr];
                bh[ni][1] = *(const uint32_t*)&Bh[rr + 8];
                bl[ni][0] = *(const uint32_t*)&Bl[rr];
                bl[ni][1] = *(const uint32_t*)&Bl[rr + 8];
            }
            #pragma unroll
            for (int mi = 0; mi < 2; mi++)
                #pragma unroll
                for (int ni = 0; ni < 4; ni++) {
                    mma_bf16(acc[mi][ni], ah[mi], bh[ni]);
                    mma_bf16(acc[mi][ni], ah[mi], bl[ni]);
                    mma_bf16(acc[mi][ni], al[mi], bh[ni]);
                }
        }
        __syncthreads();
    }

    #pragma unroll
    for (int mi = 0; mi < 2; mi++) {
        #pragma unroll
        for (int ni = 0; ni < 4; ni++) {
            const int rr = m0 + wm + mi * 16 + lg;
            const int cc = n0 + wn + ni * 8 + 2 * lc;
            *(float2*)(C + (size_t)rr * ldc + cc) =
                make_float2(acc[mi][ni][0], acc[mi][ni][1]);
            *(float2*)(C + (size_t)(rr + 8) * ldc + cc) =
                make_float2(acc[mi][ni][2], acc[mi][ni][3]);
        }
    }
}

// ---------------- q-latent RMS norm ----------------
__global__ void __launch_bounds__(256) qlat_norm_kernel(float* __restrict__ q,
                                                        const float* __restrict__ w)
{
    const int row = blockIdx.x;
    float* p = q + (size_t)row * QL;
    float4 v = *(float4*)(p + threadIdx.x * 4);
    float ssq = v.x * v.x + v.y * v.y + v.z * v.z + v.w * v.w;
    float tot = blk_sum_256(ssq);
    float inv = rsqrtf(tot * (1.f / QL) + EPSF);
    float4 wv = *(const float4*)(w + threadIdx.x * 4);
    v.x *= inv * wv.x; v.y *= inv * wv.y; v.z *= inv * wv.z; v.w *= inv * wv.w;
    *(float4*)(p + threadIdx.x * 4) = v;
}

// ---------------- per-head q norm + forward RoPE -> scaled bf16 hi/lo planes ----------------
__global__ void __launch_bounds__(256) q_post_kernel(const float* __restrict__ q,
                                                     const float* __restrict__ freqs,
                                                     uint16_t* __restrict__ qh,
                                                     uint16_t* __restrict__ qlo)
{
    const int h = blockIdx.x, s = blockIdx.y, d = threadIdx.x;
    const float* qp = q + (size_t)s * HD + h * DH;
    float v = qp[d];
    float tot = blk_sum_256(v * v);
    float nv = v * rsqrtf(tot * (1.f / DH) + EPSF);
    __shared__ float sh[DH];
    sh[d] = nv;
    __syncthreads();
    float outv = nv;
    if (d >= NOPE) {
        int p = (d - NOPE) >> 1;
        float f = freqs[s * (RR / 2) + p];
        float c = cosf(f), sn = sinf(f);
        outv = ((d & 1) == 0) ? sh[d] * c - sh[d + 1] * sn
                              : sh[d - 1] * sn + sh[d] * c;
    }
    const float v2 = outv * SCALE_F;
    uint16_t hi, lo;
    split1(v2, hi, lo);
    const size_t idx = (size_t)s * HD + h * DH + d;
    qh[idx] = hi; qlo[idx] = lo;
}

// ---------------- kv RMS norm + forward RoPE -> bf16 hi/lo planes ----------------
__global__ void __launch_bounds__(256) kv_post_kernel(const float* __restrict__ kv,
                                                      const float* __restrict__ w,
                                                      const float* __restrict__ freqs,
                                                      uint16_t* __restrict__ kvh,
                                                      uint16_t* __restrict__ kvl)
{
    const int s = blockIdx.x, d = threadIdx.x;
    const float* kp = kv + (size_t)s * DH;
    float v = kp[d];
    float tot = blk_sum_256(v * v);
    float nv = v * rsqrtf(tot * (1.f / DH) + EPSF) * w[d];
    __shared__ float sh[DH];
    sh[d] = nv;
    __syncthreads();
    float outv = nv;
    if (d >= NOPE) {
        int p = (d - NOPE) >> 1;
        float f = freqs[s * (RR / 2) + p];
        float c = cosf(f), sn = sinf(f);
        outv = ((d & 1) == 0) ? sh[d] * c - sh[d + 1] * sn
                              : sh[d - 1] * sn + sh[d] * c;
    }
    uint16_t hi, lo;
    split1(outv, hi, lo);
    kvh[s * DH + d] = hi; kvl[s * DH + d] = lo;
}

// ---------------- u16 transpose: src[2048][256] -> dst[256][2048] ----------------
__global__ void __launch_bounds__(256) transpose_u16_kernel(const uint16_t* __restrict__ s,
                                                            uint16_t* __restrict__ d)
{
    __shared__ uint16_t tl[32][34];
    const int t0 = blockIdx.x * 32, d0 = blockIdx.y * 32;
    const int tx = threadIdx.x & 31, ty = threadIdx.x >> 5;
    #pragma unroll
    for (int i = ty; i < 32; i += 8)
        tl[i][tx] = s[(size_t)(t0 + i) * DH + d0 + tx];
    __syncthreads();
    #pragma unroll
    for (int i = ty; i < 32; i += 8)
        d[(size_t)(d0 + i) * S_LEN + t0 + tx] = tl[tx][i];
}

// =================== flash attention, bf16x3 mma (GEMM-proven LDS patterns) ===================
// CTA: 64 q-rows x 1 head, 128 threads (4 warps x 16 rows). KV tile 64.
#define QSTR 264                 // u16 per Q/K row (256 + 8 pad)
#define VSTR 72                  // u16 per Vt row (64 + 8 pad)
#define PSTR 72                  // u16 per P row
#define QK_PLANE (64 * QSTR)     // 16896
#define VT_PLANE (256 * VSTR)    // 18432
#define P_PLANE  (64 * PSTR)     // 4608
#define FLASH_SMEM ((4 * QK_PLANE + 2 * VT_PLANE + 2 * P_PLANE) * 2)  // 227328 B

__global__ void __launch_bounds__(128, 1) flash_mma_kernel(
    const uint16_t* __restrict__ qh, const uint16_t* __restrict__ qlo,
    const uint16_t* __restrict__ kvh, const uint16_t* __restrict__ kvl,
    const uint16_t* __restrict__ vth, const uint16_t* __restrict__ vtl,
    const float* __restrict__ freqs, const float* __restrict__ sink,
    float* __restrict__ o)
{
    extern __shared__ __align__(16) uint16_t fsm[];
    uint16_t* Qh = fsm;
    uint16_t* Ql = fsm + QK_PLANE;
    uint16_t* Kh = fsm + 2 * QK_PLANE;
    uint16_t* Kl = fsm + 3 * QK_PLANE;
    uint16_t* Vh = fsm + 4 * QK_PLANE;
    uint16_t* Vl = fsm + 4 * QK_PLANE + VT_PLANE;
    uint16_t* Ph = fsm + 4 * QK_PLANE + 2 * VT_PLANE;
    uint16_t* Pl = Ph + P_PLANE;

    const int h = blockIdx.y;
    const int q0 = (gridDim.x - 1 - (int)blockIdx.x) * 64;  // heavy tiles first
    const int tid = threadIdx.x, lane = tid & 31, wid = tid >> 5;
    const int wq = wid * 16, lg = lane >> 2, lc = lane & 3;

    // ---- load Q tile (both planes) ----
    #pragma unroll
    for (int j = 0; j < 16; j++) {
        const int idx = tid + j * 128;
        const int r = idx >> 5, c = (idx & 31) * 8;
        const size_t g = (size_t)(q0 + r) * HD + h * DH + c;
        *(uint4*)&Qh[r * QSTR + c] = *(const uint4*)&qh[g];
        *(uint4*)&Ql[r * QSTR + c] = *(const uint4*)&qlo[g];
    }

    float oc[32][4];
    #pragma unroll
    for (int n = 0; n < 32; n++)
        #pragma unroll
        for (int r = 0; r < 4; r++) oc[n][r] = 0.f;

    const float snk = sink[h];
    float mr0 = snk, mr1 = snk, lr0 = 1.f, lr1 = 1.f;

    for (int t0 = 0; t0 <= q0; t0 += 64) {
        __syncthreads();
        // ---- load K tile [t][d] and Vt tile [d][t] ----
        #pragma unroll
        for (int j = 0; j < 16; j++) {
            const int idx = tid + j * 128;
            const int r = idx >> 5, c = (idx & 31) * 8;
            const size_t g = (size_t)(t0 + r) * DH + c;
            *(uint4*)&Kh[r * QSTR + c] = *(const uint4*)&kvh[g];
            *(uint4*)&Kl[r * QSTR + c] = *(const uint4*)&kvl[g];
        }
        #pragma unroll
        for (int j = 0; j < 16; j++) {
            const int idx = tid + j * 128;
            const int r = idx >> 3, c = (idx & 7) * 8;
            const size_t g = (size_t)r * S_LEN + t0 + c;
            *(uint4*)&Vh[r * VSTR + c] = *(const uint4*)&vth[g];
            *(uint4*)&Vl[r * VSTR + c] = *(const uint4*)&vtl[g];
        }
        __syncthreads();

        // ---- scores S[16][64], bf16x3 ----
        float sc[8][4];
        #pragma unroll
        for (int j = 0; j < 8; j++)
            #pragma unroll
            for (int r = 0; r < 4; r++) sc[j][r] = 0.f;

        #pragma unroll 4
        for (int kk = 0; kk < 256; kk += 16) {
            uint32_t ah[4], al[4];
            const int ab = (wq + lg) * QSTR + kk + 2 * lc;
            ah[0] = *(const uint32_t*)&Qh[ab];
            ah[1] = *(const uint32_t*)&Qh[ab + 8 * QSTR];
            ah[2] = *(const uint32_t*)&Qh[ab + 8];
            ah[3] = *(const uint32_t*)&Qh[ab + 8 * QSTR + 8];
            al[0] = *(const uint32_t*)&Ql[ab];
            al[1] = *(const uint32_t*)&Ql[ab + 8 * QSTR];
            al[2] = *(const uint32_t*)&Ql[ab + 8];
            al[3] = *(const uint32_t*)&Ql[ab + 8 * QSTR + 8];
            #pragma unroll
            for (int tn = 0; tn < 8; tn++) {
                const int bb = (tn * 8 + lg) * QSTR + kk + 2 * lc;
                uint32_t bh[2], bl[2];
                bh[0] = *(const uint32_t*)&Kh[bb];
                bh[1] = *(const uint32_t*)&Kh[bb + 8];
                bl[0] = *(const uint32_t*)&Kl[bb];
                bl[1] = *(const uint32_t*)&Kl[bb + 8];
                mma_bf16(sc[tn], ah, bh);
                mma_bf16(sc[tn], ah, bl);
                mma_bf16(sc[tn], al, bh);
            }
        }

        // ---- causal mask (diag tile only) ----
        if (t0 == q0) {
            const int row0 = q0 + wq + lg, row1 = row0 + 8;
            #pragma unroll
            for (int j = 0; j < 8; j++) {
                const int cb = t0 + 8 * j + 2 * lc;
                if (cb > row0)     sc[j][0] = -1e30f;
                if (cb + 1 > row0) sc[j][1] = -1e30f;
                if (cb > row1)     sc[j][2] = -1e30f;
                if (cb + 1 > row1) sc[j][3] = -1e30f;
            }
        }

        // ---- online softmax (rows lg, lg+8; reduce over 4 lanes) ----
        float mt0 = -1e30f, mt1 = -1e30f;
        #pragma unroll
        for (int j = 0; j < 8; j++) {
            mt0 = fmaxf(mt0, fmaxf(sc[j][0], sc[j][1]));
            mt1 = fmaxf(mt1, fmaxf(sc[j][2], sc[j][3]));
        }
        mt0 = fmaxf(mt0, __shfl_xor_sync(0xffffffffu, mt0, 1));
        mt0 = fmaxf(mt0, __shfl_xor_sync(0xffffffffu, mt0, 2));
        mt1 = fmaxf(mt1, __shfl_xor_sync(0xffffffffu, mt1, 1));
        mt1 = fmaxf(mt1, __shfl_xor_sync(0xffffffffu, mt1, 2));
        const float mn0 = fmaxf(mr0, mt0), mn1 = fmaxf(mr1, mt1);
        const float a0 = __expf(mr0 - mn0), a1 = __expf(mr1 - mn1);
        float rs0 = 0.f, rs1 = 0.f;
        #pragma unroll
        for (int j = 0; j < 8; j++) {
            sc[j][0] = __expf(sc[j][0] - mn0);
            sc[j][1] = __expf(sc[j][1] - mn0);
            sc[j][2] = __expf(sc[j][2] - mn1);
            sc[j][3] = __expf(sc[j][3] - mn1);
            rs0 += sc[j][0] + sc[j][1];
            rs1 += sc[j][2] + sc[j][3];
        }
        rs0 += __shfl_xor_sync(0xffffffffu, rs0, 1);
        rs0 += __shfl_xor_sync(0xffffffffu, rs0, 2);
        rs1 += __shfl_xor_sync(0xffffffffu, rs1, 1);
        rs1 += __shfl_xor_sync(0xffffffffu, rs1, 2);
        lr0 = lr0 * a0 + rs0; mr0 = mn0;
        lr1 = lr1 * a1 + rs1; mr1 = mn1;
        #pragma unroll
        for (int n = 0; n < 32; n++) {
            oc[n][0] *= a0; oc[n][1] *= a0;
            oc[n][2] *= a1; oc[n][3] *= a1;
        }

        // ---- store P hi/lo to SMEM (rows are warp-private) ----
        #pragma unroll
        for (int j = 0; j < 8; j++) {
            uint32_t h0, l0, h1, l1;
            split2(sc[j][0], sc[j][1], h0, l0);
            split2(sc[j][2], sc[j][3], h1, l1);
            const int pb = (wq + lg) * PSTR + 8 * j + 2 * lc;
            *(uint32_t*)&Ph[pb] = h0;
            *(uint32_t*)&Pl[pb] = l0;
            *(uint32_t*)&Ph[pb + 8 * PSTR] = h1;
            *(uint32_t*)&Pl[pb + 8 * PSTR] = l1;
        }
        __syncwarp();

        // ---- O += P @ V (Vt planes, GEMM B pattern) ----
        #pragma unroll
        for (int kg = 0; kg < 4; kg++) {
            uint32_t pah[4], pal[4];
            const int pb = (wq + lg) * PSTR + kg * 16 + 2 * lc;
            pah[0] = *(const uint32_t*)&Ph[pb];
            pah[1] = *(const uint32_t*)&Ph[pb + 8 * PSTR];
            pah[2] = *(const uint32_t*)&Ph[pb + 8];
            pah[3] = *(const uint32_t*)&Ph[pb + 8 * PSTR + 8];
            pal[0] = *(const uint32_t*)&Pl[pb];
            pal[1] = *(const uint32_t*)&Pl[pb + 8 * PSTR];
            pal[2] = *(const uint32_t*)&Pl[pb + 8];
            pal[3] = *(const uint32_t*)&Pl[pb + 8 * PSTR + 8];
            #pragma unroll
            for (int dg = 0; dg < 32; dg++) {
                const int vb = (dg * 8 + lg) * VSTR + kg * 16 + 2 * lc;
                uint32_t vh[2], vl[2];
                vh[0] = *(const uint32_t*)&Vh[vb];
                vh[1] = *(const uint32_t*)&Vh[vb + 8];
                vl[0] = *(const uint32_t*)&Vl[vb];
                vl[1] = *(const uint32_t*)&Vl[vb + 8];
                mma_bf16(oc[dg], pah, vh);
                mma_bf16(oc[dg], pah, vl);
                mma_bf16(oc[dg], pal, vh);
            }
        }
    }

    // ---- epilogue: 1/l, conj-RoPE on d>=192, store ----
    const float inv0 = 1.f / lr0, inv1 = 1.f / lr1;
    const int r0g = q0 + wq + lg, r1g = r0g + 8;
    float* o0 = o + (size_t)r0g * HD + h * DH;
    float* o1 = o + (size_t)r1g * HD + h * DH;
    #pragma unroll
    for (int n = 0; n < 24; n++) {
        const int col = 8 * n + 2 * lc;
        *(float2*)(o0 + col) = make_float2(oc[n][0] * inv0, oc[n][1] * inv0);
        *(float2*)(o1 + col) = make_float2(oc[n][2] * inv1, oc[n][3] * inv1);
    }
    #pragma unroll
    for (int n = 24; n < 32; n++) {
        const int col = 8 * n + 2 * lc;
        const int p = 4 * (n - 24) + lc;
        {
            const float f = freqs[r0g * (RR / 2) + p];
            const float c = cosf(f), s = sinf(f);
            const float v0 = oc[n][0] * inv0, v1 = oc[n][1] * inv0;
            *(float2*)(o0 + col) = make_float2(v0 * c + v1 * s, -v0 * s + v1 * c);
        }
        {
            const float f = freqs[r1g * (RR / 2) + p];
            const float c = cosf(f), s = sinf(f);
            const float v0 = oc[n][2] * inv1, v1 = oc[n][3] * inv1;
            *(float2*)(o1 + col) = make_float2(v0 * c + v1 * s, -v0 * s + v1 * c);
        }
    }
}

// ---------------- launch ----------------
extern "C" void kernel_launch(void* const* d_in, const int* in_sizes, int n_in,
                              void* d_out, int out_size)
{
    const float* x     = (const float*)d_in[0];
    const float* freqs = (const float*)d_in[1];
    const float* wq_a  = (const float*)d_in[2];
    const float* qnw   = (const float*)d_in[3];
    const float* wq_b  = (const float*)d_in[4];
    const float* wkv   = (const float*)d_in[5];
    const float* kvnw  = (const float*)d_in[6];
    const float* wo_a  = (const float*)d_in[7];
    const float* wo_b  = (const float*)d_in[8];
    const float* sink  = (const float*)d_in[9];
    float* out = (float*)d_out;
    (void)in_sizes; (void)n_in; (void)out_size;

    float *qlat, *qbuf, *kvbuf, *obuf, *orbuf;
    uint16_t *qhp, *qlp, *kvhp, *kvlp, *vthp, *vtlp;
    cudaGetSymbolAddress((void**)&qlat,  g_qlat);
    cudaGetSymbolAddress((void**)&qbuf,  g_q);
    cudaGetSymbolAddress((void**)&kvbuf, g_kv);
    cudaGetSymbolAddress((void**)&obuf,  g_o);
    cudaGetSymbolAddress((void**)&orbuf, g_or);
    cudaGetSymbolAddress((void**)&qhp,   g_qh);
    cudaGetSymbolAddress((void**)&qlp,   g_qlo);
    cudaGetSymbolAddress((void**)&kvhp,  g_kvh);
    cudaGetSymbolAddress((void**)&kvlp,  g_kvl);
    cudaGetSymbolAddress((void**)&vthp,  g_vth);
    cudaGetSymbolAddress((void**)&vtlp,  g_vtl);

    const int BIGN = 1 << 30;
    cudaFuncSetAttribute(gemm_bf16x3_kernel, cudaFuncAttributeMaxDynamicSharedMemorySize, GEMM_SMEM);
    cudaFuncSetAttribute(flash_mma_kernel, cudaFuncAttributeMaxDynamicSharedMemorySize, FLASH_SMEM);

    // 1) q_lat = x @ wq_a^T ; RMS norm
    gemm_bf16x3_kernel<<<dim3(QL / 128, S_LEN / 128), 512, GEMM_SMEM>>>(
        x, wq_a, qlat, HID, HID, HID, QL, BIGN, 0);
    qlat_norm_kernel<<<S_LEN, 256>>>(qlat, qnw);

    // 2) q = q_lat @ wq_b^T ; per-head norm + RoPE -> scaled bf16 planes
    gemm_bf16x3_kernel<<<dim3(HD / 128, S_LEN / 128), 512, GEMM_SMEM>>>(
        qlat, wq_b, qbuf, QL, QL, QL, HD, BIGN, 0);
    q_post_kernel<<<dim3(NH, S_LEN), 256>>>(qbuf, freqs, qhp, qlp);

    // 3) kv = rms(x @ wkv^T) ; RoPE -> bf16 planes + transposed copies
    gemm_bf16x3_kernel<<<dim3(DH / 128, S_LEN / 128), 512, GEMM_SMEM>>>(
        x, wkv, kvbuf, HID, HID, HID, DH, BIGN, 0);
    kv_post_kernel<<<S_LEN, 256>>>(kvbuf, kvnw, freqs, kvhp, kvlp);
    transpose_u16_kernel<<<dim3(S_LEN / 32, DH / 32), 256>>>(kvhp, vthp);
    transpose_u16_kernel<<<dim3(S_LEN / 32, DH / 32), 256>>>(kvlp, vtlp);

    // 4) flash attention (bf16x3 mma) with sink + conj-RoPE epilogue
    flash_mma_kernel<<<dim3(S_LEN / 64, NH), 128, FLASH_SMEM>>>(
        qhp, qlp, kvhp, kvlp, vthp, vtlp, freqs, sink, obuf);

    // 5) grouped o_r GEMM (block-diagonal wo_a)
    gemm_bf16x3_kernel<<<dim3(GO / 128, S_LEN / 128), 512, GEMM_SMEM>>>(
        obuf, wo_a, orbuf, NG * DH, HD, NG * DH, GO, ORANK, NG * DH);

    // 6) out = o_r @ wo_b^T
    gemm_bf16x3_kernel<<<dim3(HID / 128, S_LEN / 128), 512, GEMM_SMEM>>>(
        orbuf, wo_b, out, GO, GO, GO, HID, BIGN, 0);
}

// round 14
// speedup vs baseline: 3.1582x; 1.0439x over previous
#include <cuda_runtime.h>
#include <cuda_bf16.h>
#include <math.h>
#include <stdint.h>

// Problem constants
#define S_LEN 2048
#define HID   2048
#define NH    16
#define DH    256
#define RR    64
#define NOPE  192
#define QL    1024
#define ORANK 512
#define NG    4
#define HD    (NH*DH)    // 4096
#define GO    (NG*ORANK) // 2048
#define EPSF  1e-6f
#define SCALE_F 0.0625f  // 256^-0.5

// ---------------- scratch (static device globals; no allocation) ----------------
__device__ float g_qlat[S_LEN * QL];
__device__ float g_q   [S_LEN * HD];
__device__ float g_kv  [S_LEN * DH];
// bf16 hi/lo planes
__device__ uint16_t g_xh  [S_LEN * HID],  g_xl  [S_LEN * HID];
__device__ uint16_t g_wqah[QL * HID],     g_wqal[QL * HID];
__device__ uint16_t g_wqbh[HD * QL],      g_wqbl[HD * QL];
__device__ uint16_t g_wkvh[DH * HID],     g_wkvl[DH * HID];
__device__ uint16_t g_woah[GO * (HD/NG)], g_woal[GO * (HD/NG)];
__device__ uint16_t g_wobh[HID * GO],     g_wobl[HID * GO];
__device__ uint16_t g_qlh [S_LEN * QL],   g_qll [S_LEN * QL];
__device__ uint16_t g_qh  [S_LEN * HD],   g_qlo [S_LEN * HD];
__device__ uint16_t g_kvh [S_LEN * DH],   g_kvl [S_LEN * DH];
__device__ uint16_t g_vth [DH * S_LEN],   g_vtl [DH * S_LEN];
__device__ uint16_t g_oh  [S_LEN * HD],   g_ol  [S_LEN * HD];
__device__ uint16_t g_orh [S_LEN * GO],   g_orl [S_LEN * GO];

// =================== helpers ===================
__device__ __forceinline__ uint32_t smem_u32(const void* p) {
    uint32_t a;
    asm("{ .reg .u64 t; cvta.to.shared.u64 t, %1; cvt.u32.u64 %0, t; }" : "=r"(a) : "l"(p));
    return a;
}
__device__ __forceinline__ void cp_async16(uint32_t dst, const void* src) {
    asm volatile("cp.async.cg.shared.global [%0], [%1], 16;" :: "r"(dst), "l"(src));
}
#define CP_COMMIT() asm volatile("cp.async.commit_group;" ::: "memory")
#define CP_WAIT2()  asm volatile("cp.async.wait_group 2;" ::: "memory")

__device__ __forceinline__ void mma_bf16(float* d, const uint32_t* a, const uint32_t* b) {
    asm volatile(
        "mma.sync.aligned.m16n8k16.row.col.f32.bf16.bf16.f32 "
        "{%0,%1,%2,%3}, {%4,%5,%6,%7}, {%8,%9}, {%0,%1,%2,%3};"
        : "+f"(d[0]), "+f"(d[1]), "+f"(d[2]), "+f"(d[3])
        : "r"(a[0]), "r"(a[1]), "r"(a[2]), "r"(a[3]), "r"(b[0]), "r"(b[1]));
}
__device__ __forceinline__ uint32_t pack_bf16(__nv_bfloat16 a, __nv_bfloat16 b) {
    __nv_bfloat162 t;
    t.x = a; t.y = b;
    return *reinterpret_cast<uint32_t*>(&t);
}
__device__ __forceinline__ void split2(float x, float y, uint32_t& hi, uint32_t& lo) {
    __nv_bfloat16 hx = __float2bfloat16(x);
    __nv_bfloat16 hy = __float2bfloat16(y);
    __nv_bfloat16 lx = __float2bfloat16(x - __bfloat162float(hx));
    __nv_bfloat16 ly = __float2bfloat16(y - __bfloat162float(hy));
    hi = pack_bf16(hx, hy);
    lo = pack_bf16(lx, ly);
}
__device__ __forceinline__ void split1(float x, uint16_t& hi, uint16_t& lo) {
    __nv_bfloat16 hx = __float2bfloat16(x);
    __nv_bfloat16 lx = __float2bfloat16(x - __bfloat162float(hx));
    hi = *reinterpret_cast<uint16_t*>(&hx);
    lo = *reinterpret_cast<uint16_t*>(&lx);
}

// ---------------- generic fp32 -> hi/lo split ----------------
__global__ void __launch_bounds__(256) split_kernel(const float* __restrict__ in,
                                                    uint16_t* __restrict__ hi,
                                                    uint16_t* __restrict__ lo)
{
    const size_t i = ((size_t)blockIdx.x * 256 + threadIdx.x) * 4;
    float4 v = *(const float4*)(in + i);
    uint32_t h01, l01, h23, l23;
    split2(v.x, v.y, h01, l01);
    split2(v.z, v.w, h23, l23);
    *(uint2*)(hi + i) = make_uint2(h01, h23);
    *(uint2*)(lo + i) = make_uint2(l01, l23);
}

// ---------------- block reduction (256 threads) ----------------
__device__ __forceinline__ float blk_sum_256(float v) {
    __shared__ float red[8];
    #pragma unroll
    for (int o = 16; o; o >>= 1) v += __shfl_xor_sync(0xffffffffu, v, o);
    if ((threadIdx.x & 31) == 0) red[threadIdx.x >> 5] = v;
    __syncthreads();
    float t = 0.f;
    #pragma unroll
    for (int i = 0; i < 8; i++) t += red[i];
    return t;
}

// =================== bf16x3 plane GEMM: C[M,N] = A[M,K] * B[N,K]^T ===================
// Inputs pre-split hi/lo u16 planes. cp.async triple-buffered. 512 thr, 16 warps 4x4.
#define RSTR 40
#define PL_U16 (128 * RSTR)           // 5120
#define STG_U16 (4 * PL_U16)          // 20480 (40960 B per stage)
#define GEMM_SMEM (3 * STG_U16 * 2)   // 122880 B

__global__ void __launch_bounds__(512, 1) gemm_planes_kernel(
    const uint16_t* __restrict__ Ahg, const uint16_t* __restrict__ Alg,
    const uint16_t* __restrict__ Bhg, const uint16_t* __restrict__ Blg,
    float* __restrict__ C, uint16_t* __restrict__ Ch, uint16_t* __restrict__ Cl,
    int K, int lda, int ldb, int ldc, int grpN, int grpStride, int outPlanes)
{
    extern __shared__ __align__(16) uint16_t smem[];
    const int tid = threadIdx.x, lane = tid & 31, wid = tid >> 5;
    const int m0 = blockIdx.y * 128, n0 = blockIdx.x * 128;
    const size_t aoff = (size_t)(n0 / grpN) * grpStride;
    const uint16_t* Ahp = Ahg + aoff;
    const uint16_t* Alp = Alg + aoff;
    const uint32_t sbase = smem_u32(smem);

    const int wm = (wid >> 2) * 32;
    const int wn = (wid & 3) * 32;
    const int lg = lane >> 2;
    const int lc = lane & 3;

    // staging: thread -> (row, 16B segment); 128 rows x 4 segs = 512
    const int srow = tid >> 2, sseg = (tid & 3) * 8;

    float acc[2][4][4];
    #pragma unroll
    for (int mi = 0; mi < 2; mi++)
        #pragma unroll
        for (int ni = 0; ni < 4; ni++)
            #pragma unroll
            for (int r = 0; r < 4; r++) acc[mi][ni][r] = 0.f;

    const int NC = K >> 5;

    // prologue: stage chunks 0..2
    #pragma unroll
    for (int s = 0; s < 3; s++) {
        if (s < NC) {
            const int kc = s * 32;
            const uint32_t dst = sbase + (uint32_t)(s * STG_U16) * 2 + (uint32_t)(srow * RSTR + sseg) * 2;
            cp_async16(dst,                   Ahp + (size_t)(m0 + srow) * lda + kc + sseg);
            cp_async16(dst + PL_U16 * 2,      Alp + (size_t)(m0 + srow) * lda + kc + sseg);
            cp_async16(dst + 2 * PL_U16 * 2,  Bhg + (size_t)(n0 + srow) * ldb + kc + sseg);
            cp_async16(dst + 3 * PL_U16 * 2,  Blg + (size_t)(n0 + srow) * ldb + kc + sseg);
        }
        CP_COMMIT();
    }

    int stage = 0;
    for (int k = 0; k < NC; k++) {
        CP_WAIT2();
        __syncthreads();

        const uint16_t* Ah = smem + stage * STG_U16;
        const uint16_t* Al = Ah + PL_U16;
        const uint16_t* Bh = Ah + 2 * PL_U16;
        const uint16_t* Bl = Ah + 3 * PL_U16;

        #pragma unroll
        for (int kk = 0; kk < 32; kk += 16) {
            uint32_t ah[2][4], al[2][4], bh[4][2], bl[4][2];
            #pragma unroll
            for (int mi = 0; mi < 2; mi++) {
                const int rr = (wm + mi * 16 + lg) * RSTR + kk + lc * 2;
                ah[mi][0] = *(const uint32_t*)&Ah[rr];
                ah[mi][1] = *(const uint32_t*)&Ah[rr + 8 * RSTR];
                ah[mi][2] = *(const uint32_t*)&Ah[rr + 8];
                ah[mi][3] = *(const uint32_t*)&Ah[rr + 8 * RSTR + 8];
                al[mi][0] = *(const uint32_t*)&Al[rr];
                al[mi][1] = *(const uint32_t*)&Al[rr + 8 * RSTR];
                al[mi][2] = *(const uint32_t*)&Al[rr + 8];
                al[mi][3] = *(const uint32_t*)&Al[rr + 8 * RSTR + 8];
            }
            #pragma unroll
            for (int ni = 0; ni < 4; ni++) {
                const int rr = (wn + ni * 8 + lg) * RSTR + kk + lc * 2;
                bh[ni][0] = *(const uint32_t*)&Bh[rr];
                bh[ni][1] = *(const uint32_t*)&Bh[rr + 8];
                bl[ni][0] = *(const uint32_t*)&Bl[rr];
                bl[ni][1] = *(const uint32_t*)&Bl[rr + 8];
            }
            #pragma unroll
            for (int mi = 0; mi < 2; mi++)
                #pragma unroll
                for (int ni = 0; ni < 4; ni++) {
                    mma_bf16(acc[mi][ni], ah[mi], bh[ni]);
                    mma_bf16(acc[mi][ni], ah[mi], bl[ni]);
                    mma_bf16(acc[mi][ni], al[mi], bh[ni]);
                }
        }
        __syncthreads();

        // refill this stage with chunk k+3
        if (k + 3 < NC) {
            const int kc = (k + 3) * 32;
            const uint32_t dst = sbase + (uint32_t)(stage * STG_U16) * 2 + (uint32_t)(srow * RSTR + sseg) * 2;
            cp_async16(dst,                   Ahp + (size_t)(m0 + srow) * lda + kc + sseg);
            cp_async16(dst + PL_U16 * 2,      Alp + (size_t)(m0 + srow) * lda + kc + sseg);
            cp_async16(dst + 2 * PL_U16 * 2,  Bhg + (size_t)(n0 + srow) * ldb + kc + sseg);
            cp_async16(dst + 3 * PL_U16 * 2,  Blg + (size_t)(n0 + srow) * ldb + kc + sseg);
        }
        CP_COMMIT();

        stage = (stage == 2) ? 0 : stage + 1;
    }

    // epilogue
    if (!outPlanes) {
        #pragma unroll
        for (int mi = 0; mi < 2; mi++)
            #pragma unroll
            for (int ni = 0; ni < 4; ni++) {
                const int rr = m0 + wm + mi * 16 + lg;
                const int cc = n0 + wn + ni * 8 + 2 * lc;
                *(float2*)(C + (size_t)rr * ldc + cc) =
                    make_float2(acc[mi][ni][0], acc[mi][ni][1]);
                *(float2*)(C + (size_t)(rr + 8) * ldc + cc) =
                    make_float2(acc[mi][ni][2], acc[mi][ni][3]);
            }
    } else {
        #pragma unroll
        for (int mi = 0; mi < 2; mi++)
            #pragma unroll
            for (int ni = 0; ni < 4; ni++) {
                const int rr = m0 + wm + mi * 16 + lg;
                const int cc = n0 + wn + ni * 8 + 2 * lc;
                uint32_t h, l;
                split2(acc[mi][ni][0], acc[mi][ni][1], h, l);
                *(uint32_t*)&Ch[(size_t)rr * ldc + cc] = h;
                *(uint32_t*)&Cl[(size_t)rr * ldc + cc] = l;
                split2(acc[mi][ni][2], acc[mi][ni][3], h, l);
                *(uint32_t*)&Ch[(size_t)(rr + 8) * ldc + cc] = h;
                *(uint32_t*)&Cl[(size_t)(rr + 8) * ldc + cc] = l;
            }
    }
}

// ---------------- q-latent RMS norm -> bf16 planes ----------------
__global__ void __launch_bounds__(256) qlat_norm_kernel(const float* __restrict__ q,
                                                        const float* __restrict__ w,
                                                        uint16_t* __restrict__ qh,
                                                        uint16_t* __restrict__ ql)
{
    const int row = blockIdx.x;
    const float* p = q + (size_t)row * QL;
    float4 v = *(const float4*)(p + threadIdx.x * 4);
    float ssq = v.x * v.x + v.y * v.y + v.z * v.z + v.w * v.w;
    float tot = blk_sum_256(ssq);
    float inv = rsqrtf(tot * (1.f / QL) + EPSF);
    float4 wv = *(const float4*)(w + threadIdx.x * 4);
    v.x *= inv * wv.x; v.y *= inv * wv.y; v.z *= inv * wv.z; v.w *= inv * wv.w;
    uint32_t h01, l01, h23, l23;
    split2(v.x, v.y, h01, l01);
    split2(v.z, v.w, h23, l23);
    const size_t i = (size_t)row * QL + threadIdx.x * 4;
    *(uint2*)(qh + i) = make_uint2(h01, h23);
    *(uint2*)(ql + i) = make_uint2(l01, l23);
}

// ---------------- per-head q norm + forward RoPE -> scaled bf16 planes ----------------
__global__ void __launch_bounds__(256) q_post_kernel(const float* __restrict__ q,
                                                     const float* __restrict__ freqs,
                                                     uint16_t* __restrict__ qh,
                                                     uint16_t* __restrict__ qlo)
{
    const int h = blockIdx.x, s = blockIdx.y, d = threadIdx.x;
    const float* qp = q + (size_t)s * HD + h * DH;
    float v = qp[d];
    float tot = blk_sum_256(v * v);
    float nv = v * rsqrtf(tot * (1.f / DH) + EPSF);
    __shared__ float sh[DH];
    sh[d] = nv;
    __syncthreads();
    float outv = nv;
    if (d >= NOPE) {
        int p = (d - NOPE) >> 1;
        float f = freqs[s * (RR / 2) + p];
        float c = cosf(f), sn = sinf(f);
        outv = ((d & 1) == 0) ? sh[d] * c - sh[d + 1] * sn
                              : sh[d - 1] * sn + sh[d] * c;
    }
    const float v2 = outv * SCALE_F;
    uint16_t hi, lo;
    split1(v2, hi, lo);
    const size_t idx = (size_t)s * HD + h * DH + d;
    qh[idx] = hi; qlo[idx] = lo;
}

// ---------------- kv RMS norm + forward RoPE -> bf16 planes ----------------
__global__ void __launch_bounds__(256) kv_post_kernel(const float* __restrict__ kv,
                                                      const float* __restrict__ w,
                                                      const float* __restrict__ freqs,
                                                      uint16_t* __restrict__ kvh,
                                                      uint16_t* __restrict__ kvl)
{
    const int s = blockIdx.x, d = threadIdx.x;
    const float* kp = kv + (size_t)s * DH;
    float v = kp[d];
    float tot = blk_sum_256(v * v);
    float nv = v * rsqrtf(tot * (1.f / DH) + EPSF) * w[d];
    __shared__ float sh[DH];
    sh[d] = nv;
    __syncthreads();
    float outv = nv;
    if (d >= NOPE) {
        int p = (d - NOPE) >> 1;
        float f = freqs[s * (RR / 2) + p];
        float c = cosf(f), sn = sinf(f);
        outv = ((d & 1) == 0) ? sh[d] * c - sh[d + 1] * sn
                              : sh[d - 1] * sn + sh[d] * c;
    }
    uint16_t hi, lo;
    split1(outv, hi, lo);
    kvh[s * DH + d] = hi; kvl[s * DH + d] = lo;
}

// ---------------- u16 transpose: src[2048][256] -> dst[256][2048] ----------------
__global__ void __launch_bounds__(256) transpose_u16_kernel(const uint16_t* __restrict__ s,
                                                            uint16_t* __restrict__ d)
{
    __shared__ uint16_t tl[32][34];
    const int t0 = blockIdx.x * 32, d0 = blockIdx.y * 32;
    const int tx = threadIdx.x & 31, ty = threadIdx.x >> 5;
    #pragma unroll
    for (int i = ty; i < 32; i += 8)
        tl[i][tx] = s[(size_t)(t0 + i) * DH + d0 + tx];
    __syncthreads();
    #pragma unroll
    for (int i = ty; i < 32; i += 8)
        d[(size_t)(d0 + i) * S_LEN + t0 + tx] = tl[tx][i];
}

// =================== flash attention, bf16x3 mma ===================
#define QSTR 264
#define VSTR 72
#define PSTR 72
#define QK_PLANE (64 * QSTR)
#define VT_PLANE (256 * VSTR)
#define P_PLANE  (64 * PSTR)
#define FLASH_SMEM ((4 * QK_PLANE + 2 * VT_PLANE + 2 * P_PLANE) * 2)  // 227328 B

__global__ void __launch_bounds__(128, 1) flash_mma_kernel(
    const uint16_t* __restrict__ qh, const uint16_t* __restrict__ qlo,
    const uint16_t* __restrict__ kvh, const uint16_t* __restrict__ kvl,
    const uint16_t* __restrict__ vth, const uint16_t* __restrict__ vtl,
    const float* __restrict__ freqs, const float* __restrict__ sink,
    uint16_t* __restrict__ oh, uint16_t* __restrict__ ol)
{
    extern __shared__ __align__(16) uint16_t fsm[];
    uint16_t* Qh = fsm;
    uint16_t* Ql = fsm + QK_PLANE;
    uint16_t* Kh = fsm + 2 * QK_PLANE;
    uint16_t* Kl = fsm + 3 * QK_PLANE;
    uint16_t* Vh = fsm + 4 * QK_PLANE;
    uint16_t* Vl = fsm + 4 * QK_PLANE + VT_PLANE;
    uint16_t* Ph = fsm + 4 * QK_PLANE + 2 * VT_PLANE;
    uint16_t* Pl = Ph + P_PLANE;

    const int h = blockIdx.y;
    const int q0 = (gridDim.x - 1 - (int)blockIdx.x) * 64;
    const int tid = threadIdx.x, lane = tid & 31, wid = tid >> 5;
    const int wq = wid * 16, lg = lane >> 2, lc = lane & 3;

    #pragma unroll
    for (int j = 0; j < 16; j++) {
        const int idx = tid + j * 128;
        const int r = idx >> 5, c = (idx & 31) * 8;
        const size_t g = (size_t)(q0 + r) * HD + h * DH + c;
        *(uint4*)&Qh[r * QSTR + c] = *(const uint4*)&qh[g];
        *(uint4*)&Ql[r * QSTR + c] = *(const uint4*)&qlo[g];
    }

    float oc[32][4];
    #pragma unroll
    for (int n = 0; n < 32; n++)
        #pragma unroll
        for (int r = 0; r < 4; r++) oc[n][r] = 0.f;

    const float snk = sink[h];
    float mr0 = snk, mr1 = snk, lr0 = 1.f, lr1 = 1.f;

    for (int t0 = 0; t0 <= q0; t0 += 64) {
        __syncthreads();
        #pragma unroll
        for (int j = 0; j < 16; j++) {
            const int idx = tid + j * 128;
            const int r = idx >> 5, c = (idx & 31) * 8;
            const size_t g = (size_t)(t0 + r) * DH + c;
            *(uint4*)&Kh[r * QSTR + c] = *(const uint4*)&kvh[g];
            *(uint4*)&Kl[r * QSTR + c] = *(const uint4*)&kvl[g];
        }
        #pragma unroll
        for (int j = 0; j < 16; j++) {
            const int idx = tid + j * 128;
            const int r = idx >> 3, c = (idx & 7) * 8;
            const size_t g = (size_t)r * S_LEN + t0 + c;
            *(uint4*)&Vh[r * VSTR + c] = *(const uint4*)&vth[g];
            *(uint4*)&Vl[r * VSTR + c] = *(const uint4*)&vtl[g];
        }
        __syncthreads();

        float sc[8][4];
        #pragma unroll
        for (int j = 0; j < 8; j++)
            #pragma unroll
            for (int r = 0; r < 4; r++) sc[j][r] = 0.f;

        #pragma unroll 4
        for (int kk = 0; kk < 256; kk += 16) {
            uint32_t ah[4], al[4];
            const int ab = (wq + lg) * QSTR + kk + 2 * lc;
            ah[0] = *(const uint32_t*)&Qh[ab];
            ah[1] = *(const uint32_t*)&Qh[ab + 8 * QSTR];
            ah[2] = *(const uint32_t*)&Qh[ab + 8];
            ah[3] = *(const uint32_t*)&Qh[ab + 8 * QSTR + 8];
            al[0] = *(const uint32_t*)&Ql[ab];
            al[1] = *(const uint32_t*)&Ql[ab + 8 * QSTR];
            al[2] = *(const uint32_t*)&Ql[ab + 8];
            al[3] = *(const uint32_t*)&Ql[ab + 8 * QSTR + 8];
            #pragma unroll
            for (int tn = 0; tn < 8; tn++) {
                const int bb = (tn * 8 + lg) * QSTR + kk + 2 * lc;
                uint32_t bh[2], bl[2];
                bh[0] = *(const uint32_t*)&Kh[bb];
                bh[1] = *(const uint32_t*)&Kh[bb + 8];
                bl[0] = *(const uint32_t*)&Kl[bb];
                bl[1] = *(const uint32_t*)&Kl[bb + 8];
                mma_bf16(sc[tn], ah, bh);
                mma_bf16(sc[tn], ah, bl);
                mma_bf16(sc[tn], al, bh);
            }
        }

        if (t0 == q0) {
            const int row0 = q0 + wq + lg, row1 = row0 + 8;
            #pragma unroll
            for (int j = 0; j < 8; j++) {
                const int cb = t0 + 8 * j + 2 * lc;
                if (cb > row0)     sc[j][0] = -1e30f;
                if (cb + 1 > row0) sc[j][1] = -1e30f;
                if (cb > row1)     sc[j][2] = -1e30f;
                if (cb + 1 > row1) sc[j][3] = -1e30f;
            }
        }

        float mt0 = -1e30f, mt1 = -1e30f;
        #pragma unroll
        for (int j = 0; j < 8; j++) {
            mt0 = fmaxf(mt0, fmaxf(sc[j][0], sc[j][1]));
            mt1 = fmaxf(mt1, fmaxf(sc[j][2], sc[j][3]));
        }
        mt0 = fmaxf(mt0, __shfl_xor_sync(0xffffffffu, mt0, 1));
        mt0 = fmaxf(mt0, __shfl_xor_sync(0xffffffffu, mt0, 2));
        mt1 = fmaxf(mt1, __shfl_xor_sync(0xffffffffu, mt1, 1));
        mt1 = fmaxf(mt1, __shfl_xor_sync(0xffffffffu, mt1, 2));
        const float mn0 = fmaxf(mr0, mt0), mn1 = fmaxf(mr1, mt1);
        const float a0 = __expf(mr0 - mn0), a1 = __expf(mr1 - mn1);
        float rs0 = 0.f, rs1 = 0.f;
        #pragma unroll
        for (int j = 0; j < 8; j++) {
            sc[j][0] = __expf(sc[j][0] - mn0);
            sc[j][1] = __expf(sc[j][1] - mn0);
            sc[j][2] = __expf(sc[j][2] - mn1);
            sc[j][3] = __expf(sc[j][3] - mn1);
            rs0 += sc[j][0] + sc[j][1];
            rs1 += sc[j][2] + sc[j][3];
        }
        rs0 += __shfl_xor_sync(0xffffffffu, rs0, 1);
        rs0 += __shfl_xor_sync(0xffffffffu, rs0, 2);
        rs1 += __shfl_xor_sync(0xffffffffu, rs1, 1);
        rs1 += __shfl_xor_sync(0xffffffffu, rs1, 2);
        lr0 = lr0 * a0 + rs0; mr0 = mn0;
        lr1 = lr1 * a1 + rs1; mr1 = mn1;
        #pragma unroll
        for (int n = 0; n < 32; n++) {
            oc[n][0] *= a0; oc[n][1] *= a0;
            oc[n][2] *= a1; oc[n][3] *= a1;
        }

        #pragma unroll
        for (int j = 0; j < 8; j++) {
            uint32_t h0, l0, h1, l1;
            split2(sc[j][0], sc[j][1], h0, l0);
            split2(sc[j][2], sc[j][3], h1, l1);
            const int pb = (wq + lg) * PSTR + 8 * j + 2 * lc;
            *(uint32_t*)&Ph[pb] = h0;
            *(uint32_t*)&Pl[pb] = l0;
            *(uint32_t*)&Ph[pb + 8 * PSTR] = h1;
            *(uint32_t*)&Pl[pb + 8 * PSTR] = l1;
        }
        __syncwarp();

        #pragma unroll
        for (int kg = 0; kg < 4; kg++) {
            uint32_t pah[4], pal[4];
            const int pb = (wq + lg) * PSTR + kg * 16 + 2 * lc;
            pah[0] = *(const uint32_t*)&Ph[pb];
            pah[1] = *(const uint32_t*)&Ph[pb + 8 * PSTR];
            pah[2] = *(const uint32_t*)&Ph[pb + 8];
            pah[3] = *(const uint32_t*)&Ph[pb + 8 * PSTR + 8];
            pal[0] = *(const uint32_t*)&Pl[pb];
            pal[1] = *(const uint32_t*)&Pl[pb + 8 * PSTR];
            pal[2] = *(const uint32_t*)&Pl[pb + 8];
            pal[3] = *(const uint32_t*)&Pl[pb + 8 * PSTR + 8];
            #pragma unroll
            for (int dg = 0; dg < 32; dg++) {
                const int vb = (dg * 8 + lg) * VSTR + kg * 16 + 2 * lc;
                uint32_t vh[2], vl[2];
                vh[0] = *(const uint32_t*)&Vh[vb];
                vh[1] = *(const uint32_t*)&Vh[vb + 8];
                vl[0] = *(const uint32_t*)&Vl[vb];
                vl[1] = *(const uint32_t*)&Vl[vb + 8];
                mma_bf16(oc[dg], pah, vh);
                mma_bf16(oc[dg], pah, vl);
                mma_bf16(oc[dg], pal, vh);
            }
        }
    }

    // ---- epilogue: 1/l, conj-RoPE on d>=192, write o hi/lo planes ----
    const float inv0 = 1.f / lr0, inv1 = 1.f / lr1;
    const int r0g = q0 + wq + lg, r1g = r0g + 8;
    const size_t b0 = (size_t)r0g * HD + h * DH;
    const size_t b1 = (size_t)r1g * HD + h * DH;
    #pragma unroll
    for (int n = 0; n < 24; n++) {
        const int col = 8 * n + 2 * lc;
        uint32_t hh, ll;
        split2(oc[n][0] * inv0, oc[n][1] * inv0, hh, ll);
        *(uint32_t*)&oh[b0 + col] = hh;
        *(uint32_t*)&ol[b0 + col] = ll;
        split2(oc[n][2] * inv1, oc[n][3] * inv1, hh, ll);
        *(uint32_t*)&oh[b1 + col] = hh;
        *(uint32_t*)&ol[b1 + col] = ll;
    }
    #pragma unroll
    for (int n = 24; n < 32; n++) {
        const int col = 8 * n + 2 * lc;
        const int p = 4 * (n - 24) + lc;
        uint32_t hh, ll;
        {
            const float f = freqs[r0g * (RR / 2) + p];
            const float c = cosf(f), s = sinf(f);
            const float v0 = oc[n][0] * inv0, v1 = oc[n][1] * inv0;
            split2(v0 * c + v1 * s, -v0 * s + v1 * c, hh, ll);
            *(uint32_t*)&oh[b0 + col] = hh;
            *(uint32_t*)&ol[b0 + col] = ll;
        }
        {
            const float f = freqs[r1g * (RR / 2) + p];
            const float c = cosf(f), s = sinf(f);
            const float v0 = oc[n][2] * inv1, v1 = oc[n][3] * inv1;
            split2(v0 * c + v1 * s, -v0 * s + v1 * c, hh, ll);
            *(uint32_t*)&oh[b1 + col] = hh;
            *(uint32_t*)&ol[b1 + col] = ll;
        }
    }
}

// ---------------- launch ----------------
extern "C" void kernel_launch(void* const* d_in, const int* in_sizes, int n_in,
                              void* d_out, int out_size)
{
    const float* x     = (const float*)d_in[0];
    const float* freqs = (const float*)d_in[1];
    const float* wq_a  = (const float*)d_in[2];
    const float* qnw   = (const float*)d_in[3];
    const float* wq_b  = (const float*)d_in[4];
    const float* wkv   = (const float*)d_in[5];
    const float* kvnw  = (const float*)d_in[6];
    const float* wo_a  = (const float*)d_in[7];
    const float* wo_b  = (const float*)d_in[8];
    const float* sink  = (const float*)d_in[9];
    float* out = (float*)d_out;
    (void)in_sizes; (void)n_in; (void)out_size;

    float *qlat, *qbuf, *kvbuf;
    cudaGetSymbolAddress((void**)&qlat,  g_qlat);
    cudaGetSymbolAddress((void**)&qbuf,  g_q);
    cudaGetSymbolAddress((void**)&kvbuf, g_kv);
    uint16_t *xh, *xl, *wqah, *wqal, *wqbh, *wqbl, *wkvh, *wkvl, *woah, *woal, *wobh, *wobl;
    uint16_t *qlh, *qll, *qhp, *qlp, *kvhp, *kvlp, *vthp, *vtlp, *ohp, *olp, *orh, *orl;
    cudaGetSymbolAddress((void**)&xh,   g_xh);   cudaGetSymbolAddress((void**)&xl,   g_xl);
    cudaGetSymbolAddress((void**)&wqah, g_wqah); cudaGetSymbolAddress((void**)&wqal, g_wqal);
    cudaGetSymbolAddress((void**)&wqbh, g_wqbh); cudaGetSymbolAddress((void**)&wqbl, g_wqbl);
    cudaGetSymbolAddress((void**)&wkvh, g_wkvh); cudaGetSymbolAddress((void**)&wkvl, g_wkvl);
    cudaGetSymbolAddress((void**)&woah, g_woah); cudaGetSymbolAddress((void**)&woal, g_woal);
    cudaGetSymbolAddress((void**)&wobh, g_wobh); cudaGetSymbolAddress((void**)&wobl, g_wobl);
    cudaGetSymbolAddress((void**)&qlh,  g_qlh);  cudaGetSymbolAddress((void**)&qll,  g_qll);
    cudaGetSymbolAddress((void**)&qhp,  g_qh);   cudaGetSymbolAddress((void**)&qlp,  g_qlo);
    cudaGetSymbolAddress((void**)&kvhp, g_kvh);  cudaGetSymbolAddress((void**)&kvlp, g_kvl);
    cudaGetSymbolAddress((void**)&vthp, g_vth);  cudaGetSymbolAddress((void**)&vtlp, g_vtl);
    cudaGetSymbolAddress((void**)&ohp,  g_oh);   cudaGetSymbolAddress((void**)&olp,  g_ol);
    cudaGetSymbolAddress((void**)&orh,  g_orh);  cudaGetSymbolAddress((void**)&orl,  g_orl);

    const int BIGN = 1 << 30;
    cudaFuncSetAttribute(gemm_planes_kernel, cudaFuncAttributeMaxDynamicSharedMemorySize, GEMM_SMEM);
    cudaFuncSetAttribute(flash_mma_kernel, cudaFuncAttributeMaxDynamicSharedMemorySize, FLASH_SMEM);

    // 0) split inputs/weights to bf16 planes
    split_kernel<<<(S_LEN * HID) / 1024, 256>>>(x, xh, xl);
    split_kernel<<<(QL * HID) / 1024, 256>>>(wq_a, wqah, wqal);
    split_kernel<<<(HD * QL) / 1024, 256>>>(wq_b, wqbh, wqbl);
    split_kernel<<<(DH * HID) / 1024, 256>>>(wkv, wkvh, wkvl);
    split_kernel<<<(GO * (HD / NG)) / 1024, 256>>>(wo_a, woah, woal);
    split_kernel<<<(HID * GO) / 1024, 256>>>(wo_b, wobh, wobl);

    // 1) q_lat = x @ wq_a^T ; RMS norm -> qlat planes
    gemm_planes_kernel<<<dim3(QL / 128, S_LEN / 128), 512, GEMM_SMEM>>>(
        xh, xl, wqah, wqal, qlat, nullptr, nullptr, HID, HID, HID, QL, BIGN, 0, 0);
    qlat_norm_kernel<<<S_LEN, 256>>>(qlat, qnw, qlh, qll);

    // 2) q = q_lat @ wq_b^T ; per-head norm + RoPE -> q planes
    gemm_planes_kernel<<<dim3(HD / 128, S_LEN / 128), 512, GEMM_SMEM>>>(
        qlh, qll, wqbh, wqbl, qbuf, nullptr, nullptr, QL, QL, QL, HD, BIGN, 0, 0);
    q_post_kernel<<<dim3(NH, S_LEN), 256>>>(qbuf, freqs, qhp, qlp);

    // 3) kv = rms(x @ wkv^T) ; RoPE -> kv planes + transposed copies
    gemm_planes_kernel<<<dim3(DH / 128, S_LEN / 128), 512, GEMM_SMEM>>>(
        xh, xl, wkvh, wkvl, kvbuf, nullptr, nullptr, HID, HID, HID, DH, BIGN, 0, 0);
    kv_post_kernel<<<S_LEN, 256>>>(kvbuf, kvnw, freqs, kvhp, kvlp);
    transpose_u16_kernel<<<dim3(S_LEN / 32, DH / 32), 256>>>(kvhp, vthp);
    transpose_u16_kernel<<<dim3(S_LEN / 32, DH / 32), 256>>>(kvlp, vtlp);

    // 4) flash attention -> o planes
    flash_mma_kernel<<<dim3(S_LEN / 64, NH), 128, FLASH_SMEM>>>(
        qhp, qlp, kvhp, kvlp, vthp, vtlp, freqs, sink, ohp, olp);

    // 5) grouped o_r GEMM (block-diagonal wo_a) -> or planes
    gemm_planes_kernel<<<dim3(GO / 128, S_LEN / 128), 512, GEMM_SMEM>>>(
        ohp, olp, woah, woal, nullptr, orh, orl, NG * DH, HD, NG * DH, GO, ORANK, NG * DH, 1);

    // 6) out = o_r @ wo_b^T
    gemm_planes_kernel<<<dim3(HID / 128, S_LEN / 128), 512, GEMM_SMEM>>>(
        orh, orl, wobh, wobl, out, nullptr, nullptr, GO, GO, GO, HID, BIGN, 0, 0);
}